// round 1
// baseline (speedup 1.0000x reference)
#include <cuda_runtime.h>
#include <cstdint>

#define NN     100000
#define EE     1600000
#define IN_F   256
#define HID_F  128
#define OUT_F  64

// ---------------- scratch (device globals; no runtime allocation) -----------
__device__ float g_dout_inv[NN];                       // deg_out count -> deg_out^-1/2
__device__ float g_din_inv[NN];                        // deg_in  count -> deg_in^-1/2
__device__ float g_Y1  [(size_t)NN * HID_F];           // (X*dout) @ W1
__device__ float g_agg1[(size_t)NN * HID_F];           // segment_sum of Y1
__device__ float g_X2  [(size_t)NN * HID_F];           // relu(agg1*din+b1)*dout
__device__ float g_Y2  [(size_t)NN * OUT_F];           // X2 @ W2

// ---------------- helpers ---------------------------------------------------
__device__ __forceinline__ void red_add_v4(float* p, float4 v) {
    asm volatile("red.global.add.v4.f32 [%0], {%1,%2,%3,%4};"
                 :: "l"(p), "f"(v.x), "f"(v.y), "f"(v.z), "f"(v.w) : "memory");
}

// ---------------- zeroing (graph-replay safe) -------------------------------
__global__ void zero_work() {
    int i = blockIdx.x * blockDim.x + threadIdx.x;      // 3.2M threads
    float4 z = make_float4(0.f, 0.f, 0.f, 0.f);
    const int nAgg = NN * HID_F / 4;                    // 3,200,000
    if (i < nAgg)   reinterpret_cast<float4*>(g_agg1)[i] = z;
    if (i < NN / 4) {
        reinterpret_cast<float4*>(g_dout_inv)[i] = z;
        reinterpret_cast<float4*>(g_din_inv)[i]  = z;
    }
}

__global__ void zero_out(float4* out, int n4) {
    int i = blockIdx.x * blockDim.x + threadIdx.x;
    if (i < n4) out[i] = make_float4(0.f, 0.f, 0.f, 0.f);
}

// ---------------- degrees ---------------------------------------------------
__global__ void hist_kernel(const int* __restrict__ src, const int* __restrict__ dst) {
    int e = blockIdx.x * blockDim.x + threadIdx.x;
    if (e < EE) {
        atomicAdd(&g_dout_inv[src[e]], 1.0f);
        atomicAdd(&g_din_inv[dst[e]], 1.0f);
    }
}

__global__ void deg_finalize() {
    int i = blockIdx.x * blockDim.x + threadIdx.x;
    if (i < NN) {
        g_dout_inv[i] = rsqrtf(fmaxf(g_dout_inv[i], 1.0f));
        g_din_inv[i]  = rsqrtf(fmaxf(g_din_inv[i],  1.0f));
    }
}

// ---------------- tiled fp32 GEMM: C = (diag(scale?) * A) @ B ---------------
// A: [M,K] row-major, B: [K,Nn] row-major, C: [M,Nn].
template<int BM, int BN, int BK, int TM, int TN, bool SCALE, int THREADS>
__device__ __forceinline__ void gemm_body(
    const float* __restrict__ A, const float* __restrict__ B,
    const float* __restrict__ scale, float* __restrict__ C,
    int M, int K, int Nn)
{
    __shared__ float As[BK][BM + 1];   // +1 pad: conflict-lite transposed stores
    __shared__ float Bs[BK][BN];

    const int tid  = threadIdx.x;
    const int tcol = tid % (BN / TN);
    const int trow = tid / (BN / TN);
    const int m0   = blockIdx.x * BM;

    float acc[TM][TN];
#pragma unroll
    for (int i = 0; i < TM; i++)
#pragma unroll
        for (int j = 0; j < TN; j++) acc[i][j] = 0.f;

    for (int kt = 0; kt < K; kt += BK) {
        // load A tile (row-scaled), transpose into As[k][m]
#pragma unroll
        for (int i = 0; i < (BM * BK) / (4 * THREADS); i++) {
            int idx = (tid + i * THREADS) * 4;
            int r = idx / BK, c = idx % BK;
            int grow = m0 + r;
            float4 v = make_float4(0.f, 0.f, 0.f, 0.f);
            if (grow < M) {
                v = *reinterpret_cast<const float4*>(&A[(size_t)grow * K + kt + c]);
                if (SCALE) {
                    float s = scale[grow];
                    v.x *= s; v.y *= s; v.z *= s; v.w *= s;
                }
            }
            As[c + 0][r] = v.x; As[c + 1][r] = v.y;
            As[c + 2][r] = v.z; As[c + 3][r] = v.w;
        }
        // load B tile (direct copy)
#pragma unroll
        for (int i = 0; i < (BK * BN) / (4 * THREADS); i++) {
            int idx = (tid + i * THREADS) * 4;
            int kk = idx / BN, nn = idx % BN;
            *reinterpret_cast<float4*>(&Bs[kk][nn]) =
                *reinterpret_cast<const float4*>(&B[(size_t)(kt + kk) * Nn + nn]);
        }
        __syncthreads();

#pragma unroll
        for (int k = 0; k < BK; k++) {
            float a[TM];
#pragma unroll
            for (int i = 0; i < TM; i++) a[i] = As[k][trow * TM + i];
            float4 b0 = *reinterpret_cast<const float4*>(&Bs[k][tcol * TN]);
            float4 b1 = *reinterpret_cast<const float4*>(&Bs[k][tcol * TN + 4]);
            float b[TN] = {b0.x, b0.y, b0.z, b0.w, b1.x, b1.y, b1.z, b1.w};
#pragma unroll
            for (int i = 0; i < TM; i++)
#pragma unroll
                for (int j = 0; j < TN; j++) acc[i][j] += a[i] * b[j];
        }
        __syncthreads();
    }

#pragma unroll
    for (int i = 0; i < TM; i++) {
        int grow = m0 + trow * TM + i;
        if (grow < M) {
#pragma unroll
            for (int j = 0; j < TN; j += 4) {
                float4 v = make_float4(acc[i][j], acc[i][j+1], acc[i][j+2], acc[i][j+3]);
                *reinterpret_cast<float4*>(&C[(size_t)grow * Nn + tcol * TN + j]) = v;
            }
        }
    }
}

__global__ void __launch_bounds__(256) gemm1_k(const float* __restrict__ A,
                                               const float* __restrict__ W) {
    gemm_body<128, 128, 16, 8, 8, true, 256>(A, W, g_dout_inv, g_Y1, NN, IN_F, HID_F);
}

__global__ void __launch_bounds__(128) gemm2_k(const float* __restrict__ W) {
    gemm_body<128, 64, 16, 8, 8, false, 128>(g_X2, W, nullptr, g_Y2, NN, HID_F, OUT_F);
}

// ---------------- edge scatters ---------------------------------------------
// layer1: 128 floats / edge -> 1 warp / edge, 1 float4 + 1 red.v4 per lane
__global__ void scatter128(const int* __restrict__ src, const int* __restrict__ dst) {
    int w = (blockIdx.x * blockDim.x + threadIdx.x) >> 5;
    if (w >= EE) return;
    int lane = threadIdx.x & 31;
    int s = __ldg(&src[w]);
    int d = __ldg(&dst[w]);
    float4 v = *reinterpret_cast<const float4*>(&g_Y1[(size_t)s * HID_F + lane * 4]);
    red_add_v4(&g_agg1[(size_t)d * HID_F + lane * 4], v);
}

// layer2: 64 floats / edge -> 16 lanes / edge
__global__ void scatter64(const int* __restrict__ src, const int* __restrict__ dst,
                          float* __restrict__ out) {
    int t = blockIdx.x * blockDim.x + threadIdx.x;
    int e = t >> 4;
    if (e >= EE) return;
    int l = t & 15;
    int s = __ldg(&src[e]);
    int d = __ldg(&dst[e]);
    float4 v = *reinterpret_cast<const float4*>(&g_Y2[(size_t)s * OUT_F + l * 4]);
    red_add_v4(&out[(size_t)d * OUT_F + l * 4], v);
}

// ---------------- elementwise fusions ---------------------------------------
// X2 = relu(agg1 * din^-1/2 + b1) * dout^-1/2
__global__ void x2_kernel(const float* __restrict__ b1) {
    int t = blockIdx.x * blockDim.x + threadIdx.x;        // N*HID/4 threads
    const int n4 = NN * HID_F / 4;
    if (t >= n4) return;
    int row = t / (HID_F / 4);
    int c4  = t % (HID_F / 4);
    float4 v = reinterpret_cast<const float4*>(g_agg1)[t];
    float4 b = reinterpret_cast<const float4*>(b1)[c4];
    float di = g_din_inv[row], dd = g_dout_inv[row];
    v.x = fmaxf(v.x * di + b.x, 0.f) * dd;
    v.y = fmaxf(v.y * di + b.y, 0.f) * dd;
    v.z = fmaxf(v.z * di + b.z, 0.f) * dd;
    v.w = fmaxf(v.w * di + b.w, 0.f) * dd;
    reinterpret_cast<float4*>(g_X2)[t] = v;
}

// out = out * din^-1/2 + b2  (in place, no relu)
__global__ void final_kernel(float* __restrict__ out, const float* __restrict__ b2) {
    int t = blockIdx.x * blockDim.x + threadIdx.x;        // N*OUT/4 threads
    const int n4 = NN * OUT_F / 4;
    if (t >= n4) return;
    int row = t / (OUT_F / 4);
    int c4  = t % (OUT_F / 4);
    float4 v = reinterpret_cast<float4*>(out)[t];
    float4 b = reinterpret_cast<const float4*>(b2)[c4];
    float di = g_din_inv[row];
    v.x = v.x * di + b.x;
    v.y = v.y * di + b.y;
    v.z = v.z * di + b.z;
    v.w = v.w * di + b.w;
    reinterpret_cast<float4*>(out)[t] = v;
}

// ---------------- launch ----------------------------------------------------
extern "C" void kernel_launch(void* const* d_in, const int* in_sizes, int n_in,
                              void* d_out, int out_size) {
    (void)in_sizes; (void)n_in; (void)out_size;
    const float* features = (const float*)d_in[0];   // [N, 256]
    const int*   src      = (const int*)  d_in[1];   // [E]
    const int*   dst      = (const int*)  d_in[2];   // [E]
    const float* W1       = (const float*)d_in[3];   // [256, 128]
    const float* b1       = (const float*)d_in[4];   // [128]
    const float* W2       = (const float*)d_in[5];   // [128, 64]
    const float* b2       = (const float*)d_in[6];   // [64]
    float*       out      = (float*)      d_out;     // [N, 64]

    const int TPB = 256;

    // zero scratch + output accumulator
    zero_work<<<(NN * HID_F / 4 + TPB - 1) / TPB, TPB>>>();
    zero_out<<<(NN * OUT_F / 4 + TPB - 1) / TPB, TPB>>>(
        reinterpret_cast<float4*>(out), NN * OUT_F / 4);

    // degrees
    hist_kernel<<<(EE + TPB - 1) / TPB, TPB>>>(src, dst);
    deg_finalize<<<(NN + TPB - 1) / TPB, TPB>>>();

    // layer 1
    gemm1_k<<<(NN + 127) / 128, 256>>>(features, W1);
    scatter128<<<(EE * 32 + TPB - 1) / TPB, TPB>>>(src, dst);
    x2_kernel<<<(NN * HID_F / 4 + TPB - 1) / TPB, TPB>>>(b1);

    // layer 2
    gemm2_k<<<(NN + 127) / 128, 128>>>(W2);
    scatter64<<<(EE * 16 + TPB - 1) / TPB, TPB>>>(src, dst, out);
    final_kernel<<<(NN * OUT_F / 4 + TPB - 1) / TPB, TPB>>>(out, b2);
}

// round 2
// speedup vs baseline: 1.0022x; 1.0022x over previous
#include <cuda_runtime.h>
#include <cstdint>

#define NN     100000
#define EE     1600000
#define IN_F   256
#define HID_F  128
#define OUT_F  64

// ---------------- scratch (device globals; no runtime allocation) -----------
__device__ float g_dout_inv[NN];                       // deg_out count -> deg_out^-1/2
__device__ float g_din_inv[NN];                        // deg_in  count -> deg_in^-1/2
__device__ float g_Y1  [(size_t)NN * HID_F];           // (X*dout) @ W1
__device__ float g_agg1[(size_t)NN * HID_F];           // segment_sum of Y1
__device__ float g_X2  [(size_t)NN * HID_F];           // relu(agg1*din+b1)*dout
__device__ float g_Y2  [(size_t)NN * OUT_F];           // X2 @ W2

// ---------------- helpers ---------------------------------------------------
__device__ __forceinline__ void red_add_v4(float* p, float4 v) {
    asm volatile("red.global.add.v4.f32 [%0], {%1,%2,%3,%4};"
                 :: "l"(p), "f"(v.x), "f"(v.y), "f"(v.z), "f"(v.w) : "memory");
}

// ---------------- zeroing (graph-replay safe) -------------------------------
__global__ void zero_work() {
    int i = blockIdx.x * blockDim.x + threadIdx.x;      // 3.2M threads
    float4 z = make_float4(0.f, 0.f, 0.f, 0.f);
    const int nAgg = NN * HID_F / 4;                    // 3,200,000
    if (i < nAgg)   reinterpret_cast<float4*>(g_agg1)[i] = z;
    if (i < NN / 4) {
        reinterpret_cast<float4*>(g_dout_inv)[i] = z;
        reinterpret_cast<float4*>(g_din_inv)[i]  = z;
    }
}

__global__ void zero_out(float4* out, int n4) {
    int i = blockIdx.x * blockDim.x + threadIdx.x;
    if (i < n4) out[i] = make_float4(0.f, 0.f, 0.f, 0.f);
}

// ---------------- degrees ---------------------------------------------------
__global__ void hist_kernel(const int* __restrict__ src, const int* __restrict__ dst) {
    int e = blockIdx.x * blockDim.x + threadIdx.x;
    if (e < EE) {
        atomicAdd(&g_dout_inv[src[e]], 1.0f);
        atomicAdd(&g_din_inv[dst[e]], 1.0f);
    }
}

__global__ void deg_finalize() {
    int i = blockIdx.x * blockDim.x + threadIdx.x;
    if (i < NN) {
        g_dout_inv[i] = rsqrtf(fmaxf(g_dout_inv[i], 1.0f));
        g_din_inv[i]  = rsqrtf(fmaxf(g_din_inv[i],  1.0f));
    }
}

// ---------------- tiled fp32 GEMM: C = (diag(scale?) * A) @ B ---------------
// A: [M,K] row-major, B: [K,Nn] row-major, C: [M,Nn].
template<int BM, int BN, int BK, int TM, int TN, bool SCALE, int THREADS>
__device__ __forceinline__ void gemm_body(
    const float* __restrict__ A, const float* __restrict__ B,
    const float* __restrict__ scale, float* __restrict__ C,
    int M, int K, int Nn)
{
    __shared__ float As[BK][BM + 1];   // +1 pad: conflict-lite transposed stores
    __shared__ float Bs[BK][BN];

    const int tid  = threadIdx.x;
    const int tcol = tid % (BN / TN);
    const int trow = tid / (BN / TN);
    const int m0   = blockIdx.x * BM;

    float acc[TM][TN];
#pragma unroll
    for (int i = 0; i < TM; i++)
#pragma unroll
        for (int j = 0; j < TN; j++) acc[i][j] = 0.f;

    for (int kt = 0; kt < K; kt += BK) {
        // load A tile (row-scaled), transpose into As[k][m]
#pragma unroll
        for (int i = 0; i < (BM * BK) / (4 * THREADS); i++) {
            int idx = (tid + i * THREADS) * 4;
            int r = idx / BK, c = idx % BK;
            int grow = m0 + r;
            float4 v = make_float4(0.f, 0.f, 0.f, 0.f);
            if (grow < M) {
                v = *reinterpret_cast<const float4*>(&A[(size_t)grow * K + kt + c]);
                if (SCALE) {
                    float s = scale[grow];
                    v.x *= s; v.y *= s; v.z *= s; v.w *= s;
                }
            }
            As[c + 0][r] = v.x; As[c + 1][r] = v.y;
            As[c + 2][r] = v.z; As[c + 3][r] = v.w;
        }
        // load B tile (direct copy)
#pragma unroll
        for (int i = 0; i < (BK * BN) / (4 * THREADS); i++) {
            int idx = (tid + i * THREADS) * 4;
            int kk = idx / BN, nn = idx % BN;
            *reinterpret_cast<float4*>(&Bs[kk][nn]) =
                *reinterpret_cast<const float4*>(&B[(size_t)(kt + kk) * Nn + nn]);
        }
        __syncthreads();

#pragma unroll
        for (int k = 0; k < BK; k++) {
            float a[TM];
#pragma unroll
            for (int i = 0; i < TM; i++) a[i] = As[k][trow * TM + i];
            float4 b0 = *reinterpret_cast<const float4*>(&Bs[k][tcol * TN]);
            float4 b1 = *reinterpret_cast<const float4*>(&Bs[k][tcol * TN + 4]);
            float b[TN] = {b0.x, b0.y, b0.z, b0.w, b1.x, b1.y, b1.z, b1.w};
#pragma unroll
            for (int i = 0; i < TM; i++)
#pragma unroll
                for (int j = 0; j < TN; j++) acc[i][j] += a[i] * b[j];
        }
        __syncthreads();
    }

#pragma unroll
    for (int i = 0; i < TM; i++) {
        int grow = m0 + trow * TM + i;
        if (grow < M) {
#pragma unroll
            for (int j = 0; j < TN; j += 4) {
                float4 v = make_float4(acc[i][j], acc[i][j+1], acc[i][j+2], acc[i][j+3]);
                *reinterpret_cast<float4*>(&C[(size_t)grow * Nn + tcol * TN + j]) = v;
            }
        }
    }
}

__global__ void __launch_bounds__(256) gemm1_k(const float* __restrict__ A,
                                               const float* __restrict__ W) {
    gemm_body<128, 128, 16, 8, 8, true, 256>(A, W, g_dout_inv, g_Y1, NN, IN_F, HID_F);
}

__global__ void __launch_bounds__(128) gemm2_k(const float* __restrict__ W) {
    gemm_body<128, 64, 16, 8, 8, false, 128>(g_X2, W, nullptr, g_Y2, NN, HID_F, OUT_F);
}

// ---------------- edge scatters ---------------------------------------------
// layer1: 128 floats / edge -> 1 warp / edge, 1 float4 + 1 red.v4 per lane
__global__ void scatter128(const int* __restrict__ src, const int* __restrict__ dst) {
    int w = (blockIdx.x * blockDim.x + threadIdx.x) >> 5;
    if (w >= EE) return;
    int lane = threadIdx.x & 31;
    int s = __ldg(&src[w]);
    int d = __ldg(&dst[w]);
    float4 v = *reinterpret_cast<const float4*>(&g_Y1[(size_t)s * HID_F + lane * 4]);
    red_add_v4(&g_agg1[(size_t)d * HID_F + lane * 4], v);
}

// layer2: 64 floats / edge -> 16 lanes / edge
__global__ void scatter64(const int* __restrict__ src, const int* __restrict__ dst,
                          float* __restrict__ out) {
    int t = blockIdx.x * blockDim.x + threadIdx.x;
    int e = t >> 4;
    if (e >= EE) return;
    int l = t & 15;
    int s = __ldg(&src[e]);
    int d = __ldg(&dst[e]);
    float4 v = *reinterpret_cast<const float4*>(&g_Y2[(size_t)s * OUT_F + l * 4]);
    red_add_v4(&out[(size_t)d * OUT_F + l * 4], v);
}

// ---------------- elementwise fusions ---------------------------------------
// X2 = relu(agg1 * din^-1/2 + b1) * dout^-1/2
__global__ void x2_kernel(const float* __restrict__ b1) {
    int t = blockIdx.x * blockDim.x + threadIdx.x;        // N*HID/4 threads
    const int n4 = NN * HID_F / 4;
    if (t >= n4) return;
    int row = t / (HID_F / 4);
    int c4  = t % (HID_F / 4);
    float4 v = reinterpret_cast<const float4*>(g_agg1)[t];
    float4 b = reinterpret_cast<const float4*>(b1)[c4];
    float di = g_din_inv[row], dd = g_dout_inv[row];
    v.x = fmaxf(v.x * di + b.x, 0.f) * dd;
    v.y = fmaxf(v.y * di + b.y, 0.f) * dd;
    v.z = fmaxf(v.z * di + b.z, 0.f) * dd;
    v.w = fmaxf(v.w * di + b.w, 0.f) * dd;
    reinterpret_cast<float4*>(g_X2)[t] = v;
}

// out = out * din^-1/2 + b2  (in place, no relu)
__global__ void final_kernel(float* __restrict__ out, const float* __restrict__ b2) {
    int t = blockIdx.x * blockDim.x + threadIdx.x;        // N*OUT/4 threads
    const int n4 = NN * OUT_F / 4;
    if (t >= n4) return;
    int row = t / (OUT_F / 4);
    int c4  = t % (OUT_F / 4);
    float4 v = reinterpret_cast<float4*>(out)[t];
    float4 b = reinterpret_cast<const float4*>(b2)[c4];
    float di = g_din_inv[row];
    v.x = v.x * di + b.x;
    v.y = v.y * di + b.y;
    v.z = v.z * di + b.z;
    v.w = v.w * di + b.w;
    reinterpret_cast<float4*>(out)[t] = v;
}

// ---------------- launch ----------------------------------------------------
extern "C" void kernel_launch(void* const* d_in, const int* in_sizes, int n_in,
                              void* d_out, int out_size) {
    (void)in_sizes; (void)n_in; (void)out_size;
    const float* features = (const float*)d_in[0];   // [N, 256]
    const int*   src      = (const int*)  d_in[1];   // [E]
    const int*   dst      = (const int*)  d_in[2];   // [E]
    const float* W1       = (const float*)d_in[3];   // [256, 128]
    const float* b1       = (const float*)d_in[4];   // [128]
    const float* W2       = (const float*)d_in[5];   // [128, 64]
    const float* b2       = (const float*)d_in[6];   // [64]
    float*       out      = (float*)      d_out;     // [N, 64]

    const int TPB = 256;

    // zero scratch + output accumulator
    zero_work<<<(NN * HID_F / 4 + TPB - 1) / TPB, TPB>>>();
    zero_out<<<(NN * OUT_F / 4 + TPB - 1) / TPB, TPB>>>(
        reinterpret_cast<float4*>(out), NN * OUT_F / 4);

    // degrees
    hist_kernel<<<(EE + TPB - 1) / TPB, TPB>>>(src, dst);
    deg_finalize<<<(NN + TPB - 1) / TPB, TPB>>>();

    // layer 1
    gemm1_k<<<(NN + 127) / 128, 256>>>(features, W1);
    scatter128<<<(EE * 32 + TPB - 1) / TPB, TPB>>>(src, dst);
    x2_kernel<<<(NN * HID_F / 4 + TPB - 1) / TPB, TPB>>>(b1);

    // layer 2
    gemm2_k<<<(NN + 127) / 128, 128>>>(W2);
    scatter64<<<(EE * 16 + TPB - 1) / TPB, TPB>>>(src, dst, out);
    final_kernel<<<(NN * OUT_F / 4 + TPB - 1) / TPB, TPB>>>(out, b2);
}

// round 3
// speedup vs baseline: 1.4670x; 1.4638x over previous
#include <cuda_runtime.h>
#include <cstdint>

#define NN     100000
#define EE     1600000
#define IN_F   256
#define HID_F  128
#define OUT_F  64

// ---------------- scratch (device globals; no runtime allocation) -----------
__device__ int   g_deg_out[NN];
__device__ int   g_deg_in [NN];
__device__ float g_dout_inv[NN];                       // deg_out^-1/2
__device__ float g_din_inv [NN];                       // deg_in^-1/2
__device__ int   g_offs  [NN];                         // CSR row offsets (by dst)
__device__ int   g_cursor[NN];                         // fill cursors
__device__ int   g_bsums [128];                        // scan block sums
__device__ int   g_csr_src[EE];                        // src ids bucketed by dst
__device__ float g_Y1[(size_t)NN * HID_F];             // (X*dout) @ W1
__device__ float g_X2[(size_t)NN * HID_F];             // relu(agg1*din+b1)*dout
__device__ float g_Y2[(size_t)NN * OUT_F];             // X2 @ W2

// ---------------- small helpers ---------------------------------------------
__device__ __forceinline__ int warp_incl_scan(int x) {
#pragma unroll
    for (int d = 1; d < 32; d <<= 1) {
        int y = __shfl_up_sync(0xffffffffu, x, d);
        if ((threadIdx.x & 31) >= d) x += y;
    }
    return x;
}

// ---------------- degree histogram + normalizers ----------------------------
__global__ void zero_degs() {
    int i = blockIdx.x * blockDim.x + threadIdx.x;
    if (i < NN) { g_deg_out[i] = 0; g_deg_in[i] = 0; }
}

__global__ void hist_kernel(const int* __restrict__ src, const int* __restrict__ dst) {
    int e = blockIdx.x * blockDim.x + threadIdx.x;
    if (e < EE) {
        atomicAdd(&g_deg_out[src[e]], 1);
        atomicAdd(&g_deg_in [dst[e]], 1);
    }
}

__global__ void deg_finalize() {
    int i = blockIdx.x * blockDim.x + threadIdx.x;
    if (i < NN) {
        g_dout_inv[i] = rsqrtf(fmaxf((float)g_deg_out[i], 1.0f));
        g_din_inv[i]  = rsqrtf(fmaxf((float)g_deg_in[i],  1.0f));
    }
}

// ---------------- exclusive scan of g_deg_in (3 kernels) --------------------
__global__ void scan_block_k() {                        // grid 98 x 1024
    __shared__ int wsum[32];
    int i = blockIdx.x * 1024 + threadIdx.x;
    int v = (i < NN) ? g_deg_in[i] : 0;
    int x = warp_incl_scan(v);
    if ((threadIdx.x & 31) == 31) wsum[threadIdx.x >> 5] = x;
    __syncthreads();
    if (threadIdx.x < 32) {
        int w  = wsum[threadIdx.x];
        int wx = warp_incl_scan(w);
        wsum[threadIdx.x] = wx - w;                     // exclusive
        if (threadIdx.x == 31) g_bsums[blockIdx.x] = wx;
    }
    __syncthreads();
    int excl = x - v + wsum[threadIdx.x >> 5];
    if (i < NN) g_offs[i] = excl;
}

__global__ void scan_top_k(int nb) {                    // 1 x 128
    __shared__ int wsum[4];
    int t = threadIdx.x;
    int v = (t < nb) ? g_bsums[t] : 0;
    int x = warp_incl_scan(v);
    if ((t & 31) == 31) wsum[t >> 5] = x;
    __syncthreads();
    if (t == 0) {
        int run = 0;
#pragma unroll
        for (int w = 0; w < 4; w++) { int tmp = wsum[w]; wsum[w] = run; run += tmp; }
    }
    __syncthreads();
    int excl = x - v + wsum[t >> 5];
    if (t < nb) g_bsums[t] = excl;
}

__global__ void scan_add_k() {                          // grid 98 x 1024
    int i = blockIdx.x * 1024 + threadIdx.x;
    if (i < NN) {
        int o = g_offs[i] + g_bsums[blockIdx.x];
        g_offs[i]   = o;
        g_cursor[i] = o;
    }
}

// ---------------- CSR fill ---------------------------------------------------
__global__ void csr_fill(const int* __restrict__ src, const int* __restrict__ dst) {
    int e = blockIdx.x * blockDim.x + threadIdx.x;
    if (e < EE) {
        int pos = atomicAdd(&g_cursor[dst[e]], 1);
        g_csr_src[pos] = src[e];
    }
}

// ---------------- tiled fp32 GEMM: C = (diag(scale?) * A) @ B ---------------
template<int BM, int BN, int BK, int TM, int TN, bool SCALE, int THREADS>
__device__ __forceinline__ void gemm_body(
    const float* __restrict__ A, const float* __restrict__ B,
    const float* __restrict__ scale, float* __restrict__ C,
    int M, int K, int Nn)
{
    __shared__ float As[BK][BM + 1];
    __shared__ float Bs[BK][BN];

    const int tid  = threadIdx.x;
    const int tcol = tid % (BN / TN);
    const int trow = tid / (BN / TN);
    const int m0   = blockIdx.x * BM;

    float acc[TM][TN];
#pragma unroll
    for (int i = 0; i < TM; i++)
#pragma unroll
        for (int j = 0; j < TN; j++) acc[i][j] = 0.f;

    for (int kt = 0; kt < K; kt += BK) {
#pragma unroll
        for (int i = 0; i < (BM * BK) / (4 * THREADS); i++) {
            int idx = (tid + i * THREADS) * 4;
            int r = idx / BK, c = idx % BK;
            int grow = m0 + r;
            float4 v = make_float4(0.f, 0.f, 0.f, 0.f);
            if (grow < M) {
                v = *reinterpret_cast<const float4*>(&A[(size_t)grow * K + kt + c]);
                if (SCALE) {
                    float s = scale[grow];
                    v.x *= s; v.y *= s; v.z *= s; v.w *= s;
                }
            }
            As[c + 0][r] = v.x; As[c + 1][r] = v.y;
            As[c + 2][r] = v.z; As[c + 3][r] = v.w;
        }
#pragma unroll
        for (int i = 0; i < (BK * BN) / (4 * THREADS); i++) {
            int idx = (tid + i * THREADS) * 4;
            int kk = idx / BN, nn = idx % BN;
            *reinterpret_cast<float4*>(&Bs[kk][nn]) =
                *reinterpret_cast<const float4*>(&B[(size_t)(kt + kk) * Nn + nn]);
        }
        __syncthreads();

#pragma unroll
        for (int k = 0; k < BK; k++) {
            float a[TM];
#pragma unroll
            for (int i = 0; i < TM; i++) a[i] = As[k][trow * TM + i];
            float4 b0 = *reinterpret_cast<const float4*>(&Bs[k][tcol * TN]);
            float4 b1 = *reinterpret_cast<const float4*>(&Bs[k][tcol * TN + 4]);
            float b[TN] = {b0.x, b0.y, b0.z, b0.w, b1.x, b1.y, b1.z, b1.w};
#pragma unroll
            for (int i = 0; i < TM; i++)
#pragma unroll
                for (int j = 0; j < TN; j++) acc[i][j] += a[i] * b[j];
        }
        __syncthreads();
    }

#pragma unroll
    for (int i = 0; i < TM; i++) {
        int grow = m0 + trow * TM + i;
        if (grow < M) {
#pragma unroll
            for (int j = 0; j < TN; j += 4) {
                float4 v = make_float4(acc[i][j], acc[i][j+1], acc[i][j+2], acc[i][j+3]);
                *reinterpret_cast<float4*>(&C[(size_t)grow * Nn + tcol * TN + j]) = v;
            }
        }
    }
}

__global__ void __launch_bounds__(256) gemm1_k(const float* __restrict__ A,
                                               const float* __restrict__ W) {
    gemm_body<128, 128, 16, 8, 8, true, 256>(A, W, g_dout_inv, g_Y1, NN, IN_F, HID_F);
}

__global__ void __launch_bounds__(128) gemm2_k(const float* __restrict__ W) {
    gemm_body<128, 64, 16, 8, 8, false, 128>(g_X2, W, nullptr, g_Y2, NN, HID_F, OUT_F);
}

// ---------------- CSR gather, layer 1 ----------------------------------------
// warp per node; lane covers 4 of 128 feats. Fused epilogue:
// X2 = relu(sum * din + b1) * dout
__global__ void __launch_bounds__(256) gather1(const float* __restrict__ b1) {
    int node = blockIdx.x * 8 + (threadIdx.x >> 5);
    if (node >= NN) return;
    int lane  = threadIdx.x & 31;
    int start = g_offs[node];
    int cnt   = g_deg_in[node];

    float4 acc = make_float4(0.f, 0.f, 0.f, 0.f);
    for (int j0 = 0; j0 < cnt; j0 += 32) {
        int m  = min(32, cnt - j0);
        int id = (lane < m) ? __ldg(&g_csr_src[start + j0 + lane]) : 0;
        int j  = 0;
        for (; j + 4 <= m; j += 4) {
            int s0 = __shfl_sync(0xffffffffu, id, j);
            int s1 = __shfl_sync(0xffffffffu, id, j + 1);
            int s2 = __shfl_sync(0xffffffffu, id, j + 2);
            int s3 = __shfl_sync(0xffffffffu, id, j + 3);
            float4 v0 = *reinterpret_cast<const float4*>(&g_Y1[(size_t)s0 * HID_F + lane * 4]);
            float4 v1 = *reinterpret_cast<const float4*>(&g_Y1[(size_t)s1 * HID_F + lane * 4]);
            float4 v2 = *reinterpret_cast<const float4*>(&g_Y1[(size_t)s2 * HID_F + lane * 4]);
            float4 v3 = *reinterpret_cast<const float4*>(&g_Y1[(size_t)s3 * HID_F + lane * 4]);
            acc.x += v0.x + v1.x + v2.x + v3.x;
            acc.y += v0.y + v1.y + v2.y + v3.y;
            acc.z += v0.z + v1.z + v2.z + v3.z;
            acc.w += v0.w + v1.w + v2.w + v3.w;
        }
        for (; j < m; j++) {
            int s = __shfl_sync(0xffffffffu, id, j);
            float4 v = *reinterpret_cast<const float4*>(&g_Y1[(size_t)s * HID_F + lane * 4]);
            acc.x += v.x; acc.y += v.y; acc.z += v.z; acc.w += v.w;
        }
    }

    float di = g_din_inv[node], dd = g_dout_inv[node];
    float4 b = *reinterpret_cast<const float4*>(&b1[lane * 4]);
    acc.x = fmaxf(acc.x * di + b.x, 0.f) * dd;
    acc.y = fmaxf(acc.y * di + b.y, 0.f) * dd;
    acc.z = fmaxf(acc.z * di + b.z, 0.f) * dd;
    acc.w = fmaxf(acc.w * di + b.w, 0.f) * dd;
    *reinterpret_cast<float4*>(&g_X2[(size_t)node * HID_F + lane * 4]) = acc;
}

// ---------------- CSR gather, layer 2 ----------------------------------------
// warp per node; lane covers 2 of 64 feats. Fused epilogue: out = sum*din + b2
__global__ void __launch_bounds__(256) gather2(float* __restrict__ out,
                                               const float* __restrict__ b2) {
    int node = blockIdx.x * 8 + (threadIdx.x >> 5);
    if (node >= NN) return;
    int lane  = threadIdx.x & 31;
    int start = g_offs[node];
    int cnt   = g_deg_in[node];

    float2 acc = make_float2(0.f, 0.f);
    for (int j0 = 0; j0 < cnt; j0 += 32) {
        int m  = min(32, cnt - j0);
        int id = (lane < m) ? __ldg(&g_csr_src[start + j0 + lane]) : 0;
        int j  = 0;
        for (; j + 4 <= m; j += 4) {
            int s0 = __shfl_sync(0xffffffffu, id, j);
            int s1 = __shfl_sync(0xffffffffu, id, j + 1);
            int s2 = __shfl_sync(0xffffffffu, id, j + 2);
            int s3 = __shfl_sync(0xffffffffu, id, j + 3);
            float2 v0 = *reinterpret_cast<const float2*>(&g_Y2[(size_t)s0 * OUT_F + lane * 2]);
            float2 v1 = *reinterpret_cast<const float2*>(&g_Y2[(size_t)s1 * OUT_F + lane * 2]);
            float2 v2 = *reinterpret_cast<const float2*>(&g_Y2[(size_t)s2 * OUT_F + lane * 2]);
            float2 v3 = *reinterpret_cast<const float2*>(&g_Y2[(size_t)s3 * OUT_F + lane * 2]);
            acc.x += v0.x + v1.x + v2.x + v3.x;
            acc.y += v0.y + v1.y + v2.y + v3.y;
        }
        for (; j < m; j++) {
            int s = __shfl_sync(0xffffffffu, id, j);
            float2 v = *reinterpret_cast<const float2*>(&g_Y2[(size_t)s * OUT_F + lane * 2]);
            acc.x += v.x; acc.y += v.y;
        }
    }

    float di = g_din_inv[node];
    float2 b = *reinterpret_cast<const float2*>(&b2[lane * 2]);
    acc.x = acc.x * di + b.x;
    acc.y = acc.y * di + b.y;
    *reinterpret_cast<float2*>(&out[(size_t)node * OUT_F + lane * 2]) = acc;
}

// ---------------- launch ----------------------------------------------------
extern "C" void kernel_launch(void* const* d_in, const int* in_sizes, int n_in,
                              void* d_out, int out_size) {
    (void)in_sizes; (void)n_in; (void)out_size;
    const float* features = (const float*)d_in[0];   // [N, 256]
    const int*   src      = (const int*)  d_in[1];   // [E]
    const int*   dst      = (const int*)  d_in[2];   // [E]
    const float* W1       = (const float*)d_in[3];   // [256, 128]
    const float* b1       = (const float*)d_in[4];   // [128]
    const float* W2       = (const float*)d_in[5];   // [128, 64]
    const float* b2       = (const float*)d_in[6];   // [64]
    float*       out      = (float*)      d_out;     // [N, 64]

    const int TPB = 256;
    const int SCAN_BLOCKS = (NN + 1023) / 1024;      // 98

    // degrees + CSR build
    zero_degs<<<(NN + TPB - 1) / TPB, TPB>>>();
    hist_kernel<<<(EE + TPB - 1) / TPB, TPB>>>(src, dst);
    deg_finalize<<<(NN + TPB - 1) / TPB, TPB>>>();
    scan_block_k<<<SCAN_BLOCKS, 1024>>>();
    scan_top_k<<<1, 128>>>(SCAN_BLOCKS);
    scan_add_k<<<SCAN_BLOCKS, 1024>>>();
    csr_fill<<<(EE + TPB - 1) / TPB, TPB>>>(src, dst);

    // layer 1: GEMM then gather (epilogue fused into gather)
    gemm1_k<<<(NN + 127) / 128, 256>>>(features, W1);
    gather1<<<(NN + 7) / 8, TPB>>>(b1);

    // layer 2: GEMM then gather (bias+norm fused, writes d_out directly)
    gemm2_k<<<(NN + 127) / 128, 128>>>(W2);
    gather2<<<(NN + 7) / 8, TPB>>>(out, b2);
}

// round 4
// speedup vs baseline: 1.4705x; 1.0024x over previous
#include <cuda_runtime.h>
#include <cstdint>

#define NN     100000
#define EE     1600000
#define IN_F   256
#define HID_F  128
#define OUT_F  64

// ---------------- scratch (device globals; no runtime allocation) -----------
__device__ int   g_deg_out[NN];
__device__ int   g_deg_in [NN];
__device__ float g_dout_inv[NN];                       // deg_out^-1/2
__device__ float g_din_inv [NN];                       // deg_in^-1/2
__device__ int   g_offs  [NN];                         // CSR row offsets (by dst)
__device__ int   g_cursor[NN];                         // fill cursors
__device__ int   g_bsums [128];                        // scan block sums
__device__ int   g_csr_src[EE];                        // src ids bucketed by dst
__device__ float g_Y1[(size_t)NN * HID_F];             // (X*dout) @ W1
__device__ float g_X2[(size_t)NN * HID_F];             // relu(agg1*din+b1)*dout
__device__ float g_Y2[(size_t)NN * OUT_F];             // X2 @ W2

// ---------------- small helpers ---------------------------------------------
__device__ __forceinline__ int warp_incl_scan(int x) {
#pragma unroll
    for (int d = 1; d < 32; d <<= 1) {
        int y = __shfl_up_sync(0xffffffffu, x, d);
        if ((threadIdx.x & 31) >= d) x += y;
    }
    return x;
}

// ---------------- degree histogram + normalizers ----------------------------
__global__ void zero_degs() {
    int i = blockIdx.x * blockDim.x + threadIdx.x;
    if (i < NN) { g_deg_out[i] = 0; g_deg_in[i] = 0; }
}

__global__ void hist_kernel(const int* __restrict__ src, const int* __restrict__ dst) {
    int e = blockIdx.x * blockDim.x + threadIdx.x;
    if (e < EE) {
        atomicAdd(&g_deg_out[src[e]], 1);
        atomicAdd(&g_deg_in [dst[e]], 1);
    }
}

__global__ void deg_finalize() {
    int i = blockIdx.x * blockDim.x + threadIdx.x;
    if (i < NN) {
        g_dout_inv[i] = rsqrtf(fmaxf((float)g_deg_out[i], 1.0f));
        g_din_inv[i]  = rsqrtf(fmaxf((float)g_deg_in[i],  1.0f));
    }
}

// ---------------- exclusive scan of g_deg_in (3 kernels) --------------------
__global__ void scan_block_k() {                        // grid 98 x 1024
    __shared__ int wsum[32];
    int i = blockIdx.x * 1024 + threadIdx.x;
    int v = (i < NN) ? g_deg_in[i] : 0;
    int x = warp_incl_scan(v);
    if ((threadIdx.x & 31) == 31) wsum[threadIdx.x >> 5] = x;
    __syncthreads();
    if (threadIdx.x < 32) {
        int w  = wsum[threadIdx.x];
        int wx = warp_incl_scan(w);
        wsum[threadIdx.x] = wx - w;                     // exclusive
        if (threadIdx.x == 31) g_bsums[blockIdx.x] = wx;
    }
    __syncthreads();
    int excl = x - v + wsum[threadIdx.x >> 5];
    if (i < NN) g_offs[i] = excl;
}

__global__ void scan_top_k(int nb) {                    // 1 x 128
    __shared__ int wsum[4];
    int t = threadIdx.x;
    int v = (t < nb) ? g_bsums[t] : 0;
    int x = warp_incl_scan(v);
    if ((t & 31) == 31) wsum[t >> 5] = x;
    __syncthreads();
    if (t == 0) {
        int run = 0;
#pragma unroll
        for (int w = 0; w < 4; w++) { int tmp = wsum[w]; wsum[w] = run; run += tmp; }
    }
    __syncthreads();
    int excl = x - v + wsum[t >> 5];
    if (t < nb) g_bsums[t] = excl;
}

__global__ void scan_add_k() {                          // grid 98 x 1024
    int i = blockIdx.x * 1024 + threadIdx.x;
    if (i < NN) {
        int o = g_offs[i] + g_bsums[blockIdx.x];
        g_offs[i]   = o;
        g_cursor[i] = o;
    }
}

// ---------------- CSR fill ---------------------------------------------------
__global__ void csr_fill(const int* __restrict__ src, const int* __restrict__ dst) {
    int e = blockIdx.x * blockDim.x + threadIdx.x;
    if (e < EE) {
        int pos = atomicAdd(&g_cursor[dst[e]], 1);
        g_csr_src[pos] = src[e];
    }
}

// ---------------- tiled fp32 GEMM: C = (diag(scale?) * A) @ B ---------------
template<int BM, int BN, int BK, int TM, int TN, bool SCALE, int THREADS>
__device__ __forceinline__ void gemm_body(
    const float* __restrict__ A, const float* __restrict__ B,
    const float* __restrict__ scale, float* __restrict__ C,
    int M, int K, int Nn)
{
    __shared__ float As[BK][BM + 1];
    __shared__ float Bs[BK][BN];

    const int tid  = threadIdx.x;
    const int tcol = tid % (BN / TN);
    const int trow = tid / (BN / TN);
    const int m0   = blockIdx.x * BM;

    float acc[TM][TN];
#pragma unroll
    for (int i = 0; i < TM; i++)
#pragma unroll
        for (int j = 0; j < TN; j++) acc[i][j] = 0.f;

    for (int kt = 0; kt < K; kt += BK) {
#pragma unroll
        for (int i = 0; i < (BM * BK) / (4 * THREADS); i++) {
            int idx = (tid + i * THREADS) * 4;
            int r = idx / BK, c = idx % BK;
            int grow = m0 + r;
            float4 v = make_float4(0.f, 0.f, 0.f, 0.f);
            if (grow < M) {
                v = *reinterpret_cast<const float4*>(&A[(size_t)grow * K + kt + c]);
                if (SCALE) {
                    float s = scale[grow];
                    v.x *= s; v.y *= s; v.z *= s; v.w *= s;
                }
            }
            As[c + 0][r] = v.x; As[c + 1][r] = v.y;
            As[c + 2][r] = v.z; As[c + 3][r] = v.w;
        }
#pragma unroll
        for (int i = 0; i < (BK * BN) / (4 * THREADS); i++) {
            int idx = (tid + i * THREADS) * 4;
            int kk = idx / BN, nn = idx % BN;
            *reinterpret_cast<float4*>(&Bs[kk][nn]) =
                *reinterpret_cast<const float4*>(&B[(size_t)(kt + kk) * Nn + nn]);
        }
        __syncthreads();

#pragma unroll
        for (int k = 0; k < BK; k++) {
            float a[TM];
#pragma unroll
            for (int i = 0; i < TM; i++) a[i] = As[k][trow * TM + i];
            float4 b0 = *reinterpret_cast<const float4*>(&Bs[k][tcol * TN]);
            float4 b1 = *reinterpret_cast<const float4*>(&Bs[k][tcol * TN + 4]);
            float b[TN] = {b0.x, b0.y, b0.z, b0.w, b1.x, b1.y, b1.z, b1.w};
#pragma unroll
            for (int i = 0; i < TM; i++)
#pragma unroll
                for (int j = 0; j < TN; j++) acc[i][j] += a[i] * b[j];
        }
        __syncthreads();
    }

#pragma unroll
    for (int i = 0; i < TM; i++) {
        int grow = m0 + trow * TM + i;
        if (grow < M) {
#pragma unroll
            for (int j = 0; j < TN; j += 4) {
                float4 v = make_float4(acc[i][j], acc[i][j+1], acc[i][j+2], acc[i][j+3]);
                *reinterpret_cast<float4*>(&C[(size_t)grow * Nn + tcol * TN + j]) = v;
            }
        }
    }
}

__global__ void __launch_bounds__(256) gemm1_k(const float* __restrict__ A,
                                               const float* __restrict__ W) {
    gemm_body<128, 128, 16, 8, 8, true, 256>(A, W, g_dout_inv, g_Y1, NN, IN_F, HID_F);
}

__global__ void __launch_bounds__(128) gemm2_k(const float* __restrict__ W) {
    gemm_body<128, 64, 16, 8, 8, false, 128>(g_X2, W, nullptr, g_Y2, NN, HID_F, OUT_F);
}

// ---------------- CSR gather, layer 1 ----------------------------------------
// warp per node; lane covers 4 of 128 feats. Fused epilogue:
// X2 = relu(sum * din + b1) * dout
__global__ void __launch_bounds__(256) gather1(const float* __restrict__ b1) {
    int node = blockIdx.x * 8 + (threadIdx.x >> 5);
    if (node >= NN) return;
    int lane  = threadIdx.x & 31;
    int start = g_offs[node];
    int cnt   = g_deg_in[node];

    float4 acc = make_float4(0.f, 0.f, 0.f, 0.f);
    for (int j0 = 0; j0 < cnt; j0 += 32) {
        int m  = min(32, cnt - j0);
        int id = (lane < m) ? __ldg(&g_csr_src[start + j0 + lane]) : 0;
        int j  = 0;
        for (; j + 4 <= m; j += 4) {
            int s0 = __shfl_sync(0xffffffffu, id, j);
            int s1 = __shfl_sync(0xffffffffu, id, j + 1);
            int s2 = __shfl_sync(0xffffffffu, id, j + 2);
            int s3 = __shfl_sync(0xffffffffu, id, j + 3);
            float4 v0 = *reinterpret_cast<const float4*>(&g_Y1[(size_t)s0 * HID_F + lane * 4]);
            float4 v1 = *reinterpret_cast<const float4*>(&g_Y1[(size_t)s1 * HID_F + lane * 4]);
            float4 v2 = *reinterpret_cast<const float4*>(&g_Y1[(size_t)s2 * HID_F + lane * 4]);
            float4 v3 = *reinterpret_cast<const float4*>(&g_Y1[(size_t)s3 * HID_F + lane * 4]);
            acc.x += v0.x + v1.x + v2.x + v3.x;
            acc.y += v0.y + v1.y + v2.y + v3.y;
            acc.z += v0.z + v1.z + v2.z + v3.z;
            acc.w += v0.w + v1.w + v2.w + v3.w;
        }
        for (; j < m; j++) {
            int s = __shfl_sync(0xffffffffu, id, j);
            float4 v = *reinterpret_cast<const float4*>(&g_Y1[(size_t)s * HID_F + lane * 4]);
            acc.x += v.x; acc.y += v.y; acc.z += v.z; acc.w += v.w;
        }
    }

    float di = g_din_inv[node], dd = g_dout_inv[node];
    float4 b = *reinterpret_cast<const float4*>(&b1[lane * 4]);
    acc.x = fmaxf(acc.x * di + b.x, 0.f) * dd;
    acc.y = fmaxf(acc.y * di + b.y, 0.f) * dd;
    acc.z = fmaxf(acc.z * di + b.z, 0.f) * dd;
    acc.w = fmaxf(acc.w * di + b.w, 0.f) * dd;
    *reinterpret_cast<float4*>(&g_X2[(size_t)node * HID_F + lane * 4]) = acc;
}

// ---------------- CSR gather, layer 2 ----------------------------------------
// warp per node; lane covers 2 of 64 feats. Fused epilogue: out = sum*din + b2
__global__ void __launch_bounds__(256) gather2(float* __restrict__ out,
                                               const float* __restrict__ b2) {
    int node = blockIdx.x * 8 + (threadIdx.x >> 5);
    if (node >= NN) return;
    int lane  = threadIdx.x & 31;
    int start = g_offs[node];
    int cnt   = g_deg_in[node];

    float2 acc = make_float2(0.f, 0.f);
    for (int j0 = 0; j0 < cnt; j0 += 32) {
        int m  = min(32, cnt - j0);
        int id = (lane < m) ? __ldg(&g_csr_src[start + j0 + lane]) : 0;
        int j  = 0;
        for (; j + 4 <= m; j += 4) {
            int s0 = __shfl_sync(0xffffffffu, id, j);
            int s1 = __shfl_sync(0xffffffffu, id, j + 1);
            int s2 = __shfl_sync(0xffffffffu, id, j + 2);
            int s3 = __shfl_sync(0xffffffffu, id, j + 3);
            float2 v0 = *reinterpret_cast<const float2*>(&g_Y2[(size_t)s0 * OUT_F + lane * 2]);
            float2 v1 = *reinterpret_cast<const float2*>(&g_Y2[(size_t)s1 * OUT_F + lane * 2]);
            float2 v2 = *reinterpret_cast<const float2*>(&g_Y2[(size_t)s2 * OUT_F + lane * 2]);
            float2 v3 = *reinterpret_cast<const float2*>(&g_Y2[(size_t)s3 * OUT_F + lane * 2]);
            acc.x += v0.x + v1.x + v2.x + v3.x;
            acc.y += v0.y + v1.y + v2.y + v3.y;
        }
        for (; j < m; j++) {
            int s = __shfl_sync(0xffffffffu, id, j);
            float2 v = *reinterpret_cast<const float2*>(&g_Y2[(size_t)s * OUT_F + lane * 2]);
            acc.x += v.x; acc.y += v.y;
        }
    }

    float di = g_din_inv[node];
    float2 b = *reinterpret_cast<const float2*>(&b2[lane * 2]);
    acc.x = acc.x * di + b.x;
    acc.y = acc.y * di + b.y;
    *reinterpret_cast<float2*>(&out[(size_t)node * OUT_F + lane * 2]) = acc;
}

// ---------------- launch ----------------------------------------------------
extern "C" void kernel_launch(void* const* d_in, const int* in_sizes, int n_in,
                              void* d_out, int out_size) {
    (void)in_sizes; (void)n_in; (void)out_size;
    const float* features = (const float*)d_in[0];   // [N, 256]
    const int*   src      = (const int*)  d_in[1];   // [E]
    const int*   dst      = (const int*)  d_in[2];   // [E]
    const float* W1       = (const float*)d_in[3];   // [256, 128]
    const float* b1       = (const float*)d_in[4];   // [128]
    const float* W2       = (const float*)d_in[5];   // [128, 64]
    const float* b2       = (const float*)d_in[6];   // [64]
    float*       out      = (float*)      d_out;     // [N, 64]

    const int TPB = 256;
    const int SCAN_BLOCKS = (NN + 1023) / 1024;      // 98

    // degrees + CSR build
    zero_degs<<<(NN + TPB - 1) / TPB, TPB>>>();
    hist_kernel<<<(EE + TPB - 1) / TPB, TPB>>>(src, dst);
    deg_finalize<<<(NN + TPB - 1) / TPB, TPB>>>();
    scan_block_k<<<SCAN_BLOCKS, 1024>>>();
    scan_top_k<<<1, 128>>>(SCAN_BLOCKS);
    scan_add_k<<<SCAN_BLOCKS, 1024>>>();
    csr_fill<<<(EE + TPB - 1) / TPB, TPB>>>(src, dst);

    // layer 1: GEMM then gather (epilogue fused into gather)
    gemm1_k<<<(NN + 127) / 128, 256>>>(features, W1);
    gather1<<<(NN + 7) / 8, TPB>>>(b1);

    // layer 2: GEMM then gather (bias+norm fused, writes d_out directly)
    gemm2_k<<<(NN + 127) / 128, 128>>>(W2);
    gather2<<<(NN + 7) / 8, TPB>>>(out, b2);
}

// round 5
// speedup vs baseline: 1.4764x; 1.0040x over previous
#include <cuda_runtime.h>
#include <cstdint>

#define NN     100000
#define EE     1600000
#define IN_F   256
#define HID_F  128
#define OUT_F  64

// ---------------- scratch (device globals; no runtime allocation) -----------
__device__ int   g_deg_out[NN];
__device__ int   g_deg_in [NN];
__device__ float g_dout_inv[NN];                       // deg_out^-1/2
__device__ float g_din_inv [NN];                       // deg_in^-1/2
__device__ int   g_offs  [NN];                         // CSR row offsets (by dst)
__device__ int   g_cursor[NN];                         // fill cursors
__device__ int   g_bsums [128];                        // scan block sums
__device__ int   g_csr_src[EE];                        // src ids bucketed by dst
__device__ float g_Y1[(size_t)NN * HID_F];             // (X*dout) @ W1
__device__ float g_X2[(size_t)NN * HID_F];             // relu(agg1*din+b1)*dout
__device__ float g_Y2[(size_t)NN * OUT_F];             // X2 @ W2

// ---------------- small helpers ---------------------------------------------
__device__ __forceinline__ int warp_incl_scan(int x) {
#pragma unroll
    for (int d = 1; d < 32; d <<= 1) {
        int y = __shfl_up_sync(0xffffffffu, x, d);
        if ((threadIdx.x & 31) >= d) x += y;
    }
    return x;
}

// ---------------- degree histogram + normalizers ----------------------------
__global__ void zero_degs() {
    int i = blockIdx.x * blockDim.x + threadIdx.x;
    if (i < NN) { g_deg_out[i] = 0; g_deg_in[i] = 0; }
}

__global__ void hist_kernel(const int* __restrict__ src, const int* __restrict__ dst) {
    int e = blockIdx.x * blockDim.x + threadIdx.x;
    if (e < EE) {
        atomicAdd(&g_deg_out[src[e]], 1);
        atomicAdd(&g_deg_in [dst[e]], 1);
    }
}

__global__ void deg_finalize() {
    int i = blockIdx.x * blockDim.x + threadIdx.x;
    if (i < NN) {
        g_dout_inv[i] = rsqrtf(fmaxf((float)g_deg_out[i], 1.0f));
        g_din_inv[i]  = rsqrtf(fmaxf((float)g_deg_in[i],  1.0f));
    }
}

// ---------------- exclusive scan of g_deg_in (3 kernels) --------------------
__global__ void scan_block_k() {                        // grid 98 x 1024
    __shared__ int wsum[32];
    int i = blockIdx.x * 1024 + threadIdx.x;
    int v = (i < NN) ? g_deg_in[i] : 0;
    int x = warp_incl_scan(v);
    if ((threadIdx.x & 31) == 31) wsum[threadIdx.x >> 5] = x;
    __syncthreads();
    if (threadIdx.x < 32) {
        int w  = wsum[threadIdx.x];
        int wx = warp_incl_scan(w);
        wsum[threadIdx.x] = wx - w;                     // exclusive
        if (threadIdx.x == 31) g_bsums[blockIdx.x] = wx;
    }
    __syncthreads();
    int excl = x - v + wsum[threadIdx.x >> 5];
    if (i < NN) g_offs[i] = excl;
}

__global__ void scan_top_k(int nb) {                    // 1 x 128
    __shared__ int wsum[4];
    int t = threadIdx.x;
    int v = (t < nb) ? g_bsums[t] : 0;
    int x = warp_incl_scan(v);
    if ((t & 31) == 31) wsum[t >> 5] = x;
    __syncthreads();
    if (t == 0) {
        int run = 0;
#pragma unroll
        for (int w = 0; w < 4; w++) { int tmp = wsum[w]; wsum[w] = run; run += tmp; }
    }
    __syncthreads();
    int excl = x - v + wsum[t >> 5];
    if (t < nb) g_bsums[t] = excl;
}

__global__ void scan_add_k() {                          // grid 98 x 1024
    int i = blockIdx.x * 1024 + threadIdx.x;
    if (i < NN) {
        int o = g_offs[i] + g_bsums[blockIdx.x];
        g_offs[i]   = o;
        g_cursor[i] = o;
    }
}

// ---------------- CSR fill ---------------------------------------------------
__global__ void csr_fill(const int* __restrict__ src, const int* __restrict__ dst) {
    int e = blockIdx.x * blockDim.x + threadIdx.x;
    if (e < EE) {
        int pos = atomicAdd(&g_cursor[dst[e]], 1);
        g_csr_src[pos] = src[e];
    }
}

// ---------------- tiled fp32 GEMM: C = (diag(scale?) * A) @ B ---------------
template<int BM, int BN, int BK, int TM, int TN, bool SCALE, int THREADS>
__device__ __forceinline__ void gemm_body(
    const float* __restrict__ A, const float* __restrict__ B,
    const float* __restrict__ scale, float* __restrict__ C,
    int M, int K, int Nn)
{
    __shared__ float As[BK][BM + 1];
    __shared__ float Bs[BK][BN];

    const int tid  = threadIdx.x;
    const int tcol = tid % (BN / TN);
    const int trow = tid / (BN / TN);
    const int m0   = blockIdx.x * BM;

    float acc[TM][TN];
#pragma unroll
    for (int i = 0; i < TM; i++)
#pragma unroll
        for (int j = 0; j < TN; j++) acc[i][j] = 0.f;

    for (int kt = 0; kt < K; kt += BK) {
#pragma unroll
        for (int i = 0; i < (BM * BK) / (4 * THREADS); i++) {
            int idx = (tid + i * THREADS) * 4;
            int r = idx / BK, c = idx % BK;
            int grow = m0 + r;
            float4 v = make_float4(0.f, 0.f, 0.f, 0.f);
            if (grow < M) {
                v = *reinterpret_cast<const float4*>(&A[(size_t)grow * K + kt + c]);
                if (SCALE) {
                    float s = scale[grow];
                    v.x *= s; v.y *= s; v.z *= s; v.w *= s;
                }
            }
            As[c + 0][r] = v.x; As[c + 1][r] = v.y;
            As[c + 2][r] = v.z; As[c + 3][r] = v.w;
        }
#pragma unroll
        for (int i = 0; i < (BK * BN) / (4 * THREADS); i++) {
            int idx = (tid + i * THREADS) * 4;
            int kk = idx / BN, nn = idx % BN;
            *reinterpret_cast<float4*>(&Bs[kk][nn]) =
                *reinterpret_cast<const float4*>(&B[(size_t)(kt + kk) * Nn + nn]);
        }
        __syncthreads();

#pragma unroll
        for (int k = 0; k < BK; k++) {
            float a[TM];
#pragma unroll
            for (int i = 0; i < TM; i++) a[i] = As[k][trow * TM + i];
            float4 b0 = *reinterpret_cast<const float4*>(&Bs[k][tcol * TN]);
            float4 b1 = *reinterpret_cast<const float4*>(&Bs[k][tcol * TN + 4]);
            float b[TN] = {b0.x, b0.y, b0.z, b0.w, b1.x, b1.y, b1.z, b1.w};
#pragma unroll
            for (int i = 0; i < TM; i++)
#pragma unroll
                for (int j = 0; j < TN; j++) acc[i][j] += a[i] * b[j];
        }
        __syncthreads();
    }

#pragma unroll
    for (int i = 0; i < TM; i++) {
        int grow = m0 + trow * TM + i;
        if (grow < M) {
#pragma unroll
            for (int j = 0; j < TN; j += 4) {
                float4 v = make_float4(acc[i][j], acc[i][j+1], acc[i][j+2], acc[i][j+3]);
                *reinterpret_cast<float4*>(&C[(size_t)grow * Nn + tcol * TN + j]) = v;
            }
        }
    }
}

__global__ void __launch_bounds__(256) gemm1_k(const float* __restrict__ A,
                                               const float* __restrict__ W) {
    gemm_body<128, 128, 16, 8, 8, true, 256>(A, W, g_dout_inv, g_Y1, NN, IN_F, HID_F);
}

__global__ void __launch_bounds__(128) gemm2_k(const float* __restrict__ W) {
    gemm_body<128, 64, 16, 8, 8, false, 128>(g_X2, W, nullptr, g_Y2, NN, HID_F, OUT_F);
}

// ---------------- CSR gather, layer 1 ----------------------------------------
// warp per node; lane covers 4 of 128 feats. Fused epilogue:
// X2 = relu(sum * din + b1) * dout
__global__ void __launch_bounds__(256) gather1(const float* __restrict__ b1) {
    int node = blockIdx.x * 8 + (threadIdx.x >> 5);
    if (node >= NN) return;
    int lane  = threadIdx.x & 31;
    int start = g_offs[node];
    int cnt   = g_deg_in[node];

    float4 acc = make_float4(0.f, 0.f, 0.f, 0.f);
    for (int j0 = 0; j0 < cnt; j0 += 32) {
        int m  = min(32, cnt - j0);
        int id = (lane < m) ? __ldg(&g_csr_src[start + j0 + lane]) : 0;
        int j  = 0;
        for (; j + 4 <= m; j += 4) {
            int s0 = __shfl_sync(0xffffffffu, id, j);
            int s1 = __shfl_sync(0xffffffffu, id, j + 1);
            int s2 = __shfl_sync(0xffffffffu, id, j + 2);
            int s3 = __shfl_sync(0xffffffffu, id, j + 3);
            float4 v0 = *reinterpret_cast<const float4*>(&g_Y1[(size_t)s0 * HID_F + lane * 4]);
            float4 v1 = *reinterpret_cast<const float4*>(&g_Y1[(size_t)s1 * HID_F + lane * 4]);
            float4 v2 = *reinterpret_cast<const float4*>(&g_Y1[(size_t)s2 * HID_F + lane * 4]);
            float4 v3 = *reinterpret_cast<const float4*>(&g_Y1[(size_t)s3 * HID_F + lane * 4]);
            acc.x += v0.x + v1.x + v2.x + v3.x;
            acc.y += v0.y + v1.y + v2.y + v3.y;
            acc.z += v0.z + v1.z + v2.z + v3.z;
            acc.w += v0.w + v1.w + v2.w + v3.w;
        }
        for (; j < m; j++) {
            int s = __shfl_sync(0xffffffffu, id, j);
            float4 v = *reinterpret_cast<const float4*>(&g_Y1[(size_t)s * HID_F + lane * 4]);
            acc.x += v.x; acc.y += v.y; acc.z += v.z; acc.w += v.w;
        }
    }

    float di = g_din_inv[node], dd = g_dout_inv[node];
    float4 b = *reinterpret_cast<const float4*>(&b1[lane * 4]);
    acc.x = fmaxf(acc.x * di + b.x, 0.f) * dd;
    acc.y = fmaxf(acc.y * di + b.y, 0.f) * dd;
    acc.z = fmaxf(acc.z * di + b.z, 0.f) * dd;
    acc.w = fmaxf(acc.w * di + b.w, 0.f) * dd;
    *reinterpret_cast<float4*>(&g_X2[(size_t)node * HID_F + lane * 4]) = acc;
}

// ---------------- CSR gather, layer 2 ----------------------------------------
// warp per node; lane covers 2 of 64 feats. Fused epilogue: out = sum*din + b2
__global__ void __launch_bounds__(256) gather2(float* __restrict__ out,
                                               const float* __restrict__ b2) {
    int node = blockIdx.x * 8 + (threadIdx.x >> 5);
    if (node >= NN) return;
    int lane  = threadIdx.x & 31;
    int start = g_offs[node];
    int cnt   = g_deg_in[node];

    float2 acc = make_float2(0.f, 0.f);
    for (int j0 = 0; j0 < cnt; j0 += 32) {
        int m  = min(32, cnt - j0);
        int id = (lane < m) ? __ldg(&g_csr_src[start + j0 + lane]) : 0;
        int j  = 0;
        for (; j + 4 <= m; j += 4) {
            int s0 = __shfl_sync(0xffffffffu, id, j);
            int s1 = __shfl_sync(0xffffffffu, id, j + 1);
            int s2 = __shfl_sync(0xffffffffu, id, j + 2);
            int s3 = __shfl_sync(0xffffffffu, id, j + 3);
            float2 v0 = *reinterpret_cast<const float2*>(&g_Y2[(size_t)s0 * OUT_F + lane * 2]);
            float2 v1 = *reinterpret_cast<const float2*>(&g_Y2[(size_t)s1 * OUT_F + lane * 2]);
            float2 v2 = *reinterpret_cast<const float2*>(&g_Y2[(size_t)s2 * OUT_F + lane * 2]);
            float2 v3 = *reinterpret_cast<const float2*>(&g_Y2[(size_t)s3 * OUT_F + lane * 2]);
            acc.x += v0.x + v1.x + v2.x + v3.x;
            acc.y += v0.y + v1.y + v2.y + v3.y;
        }
        for (; j < m; j++) {
            int s = __shfl_sync(0xffffffffu, id, j);
            float2 v = *reinterpret_cast<const float2*>(&g_Y2[(size_t)s * OUT_F + lane * 2]);
            acc.x += v.x; acc.y += v.y;
        }
    }

    float di = g_din_inv[node];
    float2 b = *reinterpret_cast<const float2*>(&b2[lane * 2]);
    acc.x = acc.x * di + b.x;
    acc.y = acc.y * di + b.y;
    *reinterpret_cast<float2*>(&out[(size_t)node * OUT_F + lane * 2]) = acc;
}

// ---------------- launch ----------------------------------------------------
extern "C" void kernel_launch(void* const* d_in, const int* in_sizes, int n_in,
                              void* d_out, int out_size) {
    (void)in_sizes; (void)n_in; (void)out_size;
    const float* features = (const float*)d_in[0];   // [N, 256]
    const int*   src      = (const int*)  d_in[1];   // [E]
    const int*   dst      = (const int*)  d_in[2];   // [E]
    const float* W1       = (const float*)d_in[3];   // [256, 128]
    const float* b1       = (const float*)d_in[4];   // [128]
    const float* W2       = (const float*)d_in[5];   // [128, 64]
    const float* b2       = (const float*)d_in[6];   // [64]
    float*       out      = (float*)      d_out;     // [N, 64]

    const int TPB = 256;
    const int SCAN_BLOCKS = (NN + 1023) / 1024;      // 98

    // degrees + CSR build
    zero_degs<<<(NN + TPB - 1) / TPB, TPB>>>();
    hist_kernel<<<(EE + TPB - 1) / TPB, TPB>>>(src, dst);
    deg_finalize<<<(NN + TPB - 1) / TPB, TPB>>>();
    scan_block_k<<<SCAN_BLOCKS, 1024>>>();
    scan_top_k<<<1, 128>>>(SCAN_BLOCKS);
    scan_add_k<<<SCAN_BLOCKS, 1024>>>();
    csr_fill<<<(EE + TPB - 1) / TPB, TPB>>>(src, dst);

    // layer 1: GEMM then gather (epilogue fused into gather)
    gemm1_k<<<(NN + 127) / 128, 256>>>(features, W1);
    gather1<<<(NN + 7) / 8, TPB>>>(b1);

    // layer 2: GEMM then gather (bias+norm fused, writes d_out directly)
    gemm2_k<<<(NN + 127) / 128, 128>>>(W2);
    gather2<<<(NN + 7) / 8, TPB>>>(out, b2);
}

// round 8
// speedup vs baseline: 1.9852x; 1.3447x over previous
#include <cuda_runtime.h>
#include <cuda_bf16.h>
#include <cstdint>

#define NN     100000
#define EE     1600000
#define IN_F   256
#define HID_F  128
#define OUT_F  64

// ---------------- scratch (device globals; no runtime allocation) -----------
__device__ int   g_deg_out[NN];
__device__ int   g_deg_in [NN];
__device__ float g_dout_inv[NN];
__device__ float g_din_inv [NN];
__device__ int   g_offs  [NN];
__device__ int   g_cursor[NN];
__device__ int   g_bsums [128];
__device__ int   g_csr_src[EE];
__device__ float g_Y1[(size_t)NN * HID_F];                       // layer1 GEMM out
__device__ __align__(16) uint16_t g_X2h[(size_t)NN * HID_F];     // X2 hi (bf16)
__device__ __align__(16) uint16_t g_X2l[(size_t)NN * HID_F];     // X2 lo (bf16)
__device__ float g_Y2[(size_t)NN * OUT_F];                       // layer2 GEMM out
__device__ __align__(16) uint16_t g_W1Th[HID_F * IN_F];          // W1^T hi  [n][k]
__device__ __align__(16) uint16_t g_W1Tl[HID_F * IN_F];          // W1^T lo
__device__ __align__(16) uint16_t g_W2Th[OUT_F * HID_F];         // W2^T hi  [n][k]
__device__ __align__(16) uint16_t g_W2Tl[OUT_F * HID_F];         // W2^T lo

// ---------------- helpers ---------------------------------------------------
__device__ __forceinline__ int warp_incl_scan(int x) {
#pragma unroll
    for (int d = 1; d < 32; d <<= 1) {
        int y = __shfl_up_sync(0xffffffffu, x, d);
        if ((threadIdx.x & 31) >= d) x += y;
    }
    return x;
}

// split fp32 pair -> packed bf16 hi / lo (x in low 16 bits)
__device__ __forceinline__ void split2(float x, float y, uint32_t& h, uint32_t& l) {
    __nv_bfloat16 hx = __float2bfloat16(x);
    __nv_bfloat16 hy = __float2bfloat16(y);
    __nv_bfloat16 lx = __float2bfloat16(x - __bfloat162float(hx));
    __nv_bfloat16 ly = __float2bfloat16(y - __bfloat162float(hy));
    h = (uint32_t)__bfloat16_as_ushort(hx) | ((uint32_t)__bfloat16_as_ushort(hy) << 16);
    l = (uint32_t)__bfloat16_as_ushort(lx) | ((uint32_t)__bfloat16_as_ushort(ly) << 16);
}

__device__ __forceinline__ void mma_bf16(float* c, const uint32_t* a, const uint32_t* b) {
    asm volatile(
        "mma.sync.aligned.m16n8k16.row.col.f32.bf16.bf16.f32 "
        "{%0,%1,%2,%3}, {%4,%5,%6,%7}, {%8,%9}, {%0,%1,%2,%3};\n"
        : "+f"(c[0]), "+f"(c[1]), "+f"(c[2]), "+f"(c[3])
        : "r"(a[0]), "r"(a[1]), "r"(a[2]), "r"(a[3]), "r"(b[0]), "r"(b[1]));
}

// ---------------- degrees / scan / CSR --------------------------------------
__global__ void zero_degs() {
    int i = blockIdx.x * blockDim.x + threadIdx.x;
    if (i < NN) { g_deg_out[i] = 0; g_deg_in[i] = 0; }
}

__global__ void hist_kernel(const int* __restrict__ src, const int* __restrict__ dst) {
    int e = blockIdx.x * blockDim.x + threadIdx.x;
    if (e < EE) {
        atomicAdd(&g_deg_out[src[e]], 1);
        atomicAdd(&g_deg_in [dst[e]], 1);
    }
}

__global__ void deg_finalize() {
    int i = blockIdx.x * blockDim.x + threadIdx.x;
    if (i < NN) {
        g_dout_inv[i] = rsqrtf(fmaxf((float)g_deg_out[i], 1.0f));
        g_din_inv[i]  = rsqrtf(fmaxf((float)g_deg_in[i],  1.0f));
    }
}

__global__ void scan_block_k() {
    __shared__ int wsum[32];
    int i = blockIdx.x * 1024 + threadIdx.x;
    int v = (i < NN) ? g_deg_in[i] : 0;
    int x = warp_incl_scan(v);
    if ((threadIdx.x & 31) == 31) wsum[threadIdx.x >> 5] = x;
    __syncthreads();
    if (threadIdx.x < 32) {
        int w  = wsum[threadIdx.x];
        int wx = warp_incl_scan(w);
        wsum[threadIdx.x] = wx - w;
        if (threadIdx.x == 31) g_bsums[blockIdx.x] = wx;
    }
    __syncthreads();
    int excl = x - v + wsum[threadIdx.x >> 5];
    if (i < NN) g_offs[i] = excl;
}

__global__ void scan_top_k(int nb) {
    __shared__ int wsum[4];
    int t = threadIdx.x;
    int v = (t < nb) ? g_bsums[t] : 0;
    int x = warp_incl_scan(v);
    if ((t & 31) == 31) wsum[t >> 5] = x;
    __syncthreads();
    if (t == 0) {
        int run = 0;
#pragma unroll
        for (int w = 0; w < 4; w++) { int tmp = wsum[w]; wsum[w] = run; run += tmp; }
    }
    __syncthreads();
    int excl = x - v + wsum[t >> 5];
    if (t < nb) g_bsums[t] = excl;
}

__global__ void scan_add_k() {
    int i = blockIdx.x * 1024 + threadIdx.x;
    if (i < NN) {
        int o = g_offs[i] + g_bsums[blockIdx.x];
        g_offs[i]   = o;
        g_cursor[i] = o;
    }
}

__global__ void csr_fill(const int* __restrict__ src, const int* __restrict__ dst) {
    int e = blockIdx.x * blockDim.x + threadIdx.x;
    if (e < EE) {
        int pos = atomicAdd(&g_cursor[dst[e]], 1);
        g_csr_src[pos] = src[e];
    }
}

// ---------------- weight split/transpose ------------------------------------
__global__ void split_w1(const float* __restrict__ W1) {       // [256,128] -> [128][256]
    int idx = blockIdx.x * blockDim.x + threadIdx.x;
    if (idx < IN_F * HID_F) {
        int k = idx / HID_F, n = idx % HID_F;
        float v = W1[idx];
        __nv_bfloat16 h = __float2bfloat16(v);
        __nv_bfloat16 l = __float2bfloat16(v - __bfloat162float(h));
        g_W1Th[n * IN_F + k] = __bfloat16_as_ushort(h);
        g_W1Tl[n * IN_F + k] = __bfloat16_as_ushort(l);
    }
}

__global__ void split_w2(const float* __restrict__ W2) {       // [128,64] -> [64][128]
    int idx = blockIdx.x * blockDim.x + threadIdx.x;
    if (idx < HID_F * OUT_F) {
        int k = idx / OUT_F, n = idx % OUT_F;
        float v = W2[idx];
        __nv_bfloat16 h = __float2bfloat16(v);
        __nv_bfloat16 l = __float2bfloat16(v - __bfloat162float(h));
        g_W2Th[n * HID_F + k] = __bfloat16_as_ushort(h);
        g_W2Tl[n * HID_F + k] = __bfloat16_as_ushort(l);
    }
}

// ---------------- GEMM1: Y1 = (X * dout) @ W1, split-bf16 tensor cores ------
// BM=64, BN=128, BK=32, 256 threads (8 warps, 2x4), warp tile 32x32.
#define AST 40   // padded smem row stride (bf16 elems) -> conflict-free frag loads
__global__ void __launch_bounds__(256) gemm1_k(const float* __restrict__ A) {
    __shared__ uint16_t As_h[64 * AST],  As_l[64 * AST];
    __shared__ uint16_t Bs_h[128 * AST], Bs_l[128 * AST];

    const int tid  = threadIdx.x;
    const int lane = tid & 31;
    const int wid  = tid >> 5;
    const int wm   = wid >> 2;                 // 0..1
    const int wn   = wid & 3;                  // 0..3
    const int g    = lane >> 2;
    const int tq   = lane & 3;
    const int m0   = blockIdx.x * 64;

    float acc[2][4][4];
#pragma unroll
    for (int mi = 0; mi < 2; mi++)
#pragma unroll
        for (int ni = 0; ni < 4; ni++)
#pragma unroll
            for (int r = 0; r < 4; r++) acc[mi][ni][r] = 0.f;

    for (int kt = 0; kt < IN_F; kt += 32) {
        // A tile: 64x32 fp32 -> scale -> split bf16. 512 float4, 2 per thread.
#pragma unroll
        for (int i = 0; i < 2; i++) {
            int idx = tid + i * 256;
            int r = idx >> 3, c = idx & 7;
            int grow = m0 + r;
            float4 v = make_float4(0.f, 0.f, 0.f, 0.f);
            if (grow < NN) {
                v = *reinterpret_cast<const float4*>(&A[(size_t)grow * IN_F + kt + c * 4]);
                float s = g_dout_inv[grow];
                v.x *= s; v.y *= s; v.z *= s; v.w *= s;
            }
            uint32_t h01, l01, h23, l23;
            split2(v.x, v.y, h01, l01);
            split2(v.z, v.w, h23, l23);
            *reinterpret_cast<uint32_t*>(&As_h[r * AST + c * 4])     = h01;
            *reinterpret_cast<uint32_t*>(&As_h[r * AST + c * 4 + 2]) = h23;
            *reinterpret_cast<uint32_t*>(&As_l[r * AST + c * 4])     = l01;
            *reinterpret_cast<uint32_t*>(&As_l[r * AST + c * 4 + 2]) = l23;
        }
        // B tile: 128 rows x 32 bf16 from pre-split W1^T. 512 uint4, 2 per thread.
#pragma unroll
        for (int i = 0; i < 2; i++) {
            int idx = tid + i * 256;
            int n = idx >> 2, c = idx & 3;
            *reinterpret_cast<uint4*>(&Bs_h[n * AST + c * 8]) =
                *reinterpret_cast<const uint4*>(&g_W1Th[n * IN_F + kt + c * 8]);
            *reinterpret_cast<uint4*>(&Bs_l[n * AST + c * 8]) =
                *reinterpret_cast<const uint4*>(&g_W1Tl[n * IN_F + kt + c * 8]);
        }
        __syncthreads();

#pragma unroll
        for (int ks = 0; ks < 2; ks++) {
            uint32_t ah[2][4], al[2][4], bh[4][2], bl[4][2];
#pragma unroll
            for (int mi = 0; mi < 2; mi++) {
                const uint16_t* pH = &As_h[(wm * 32 + mi * 16 + g) * AST + ks * 16 + tq * 2];
                const uint16_t* pL = &As_l[(wm * 32 + mi * 16 + g) * AST + ks * 16 + tq * 2];
                ah[mi][0] = *reinterpret_cast<const uint32_t*>(pH);
                ah[mi][1] = *reinterpret_cast<const uint32_t*>(pH + 8 * AST);
                ah[mi][2] = *reinterpret_cast<const uint32_t*>(pH + 8);
                ah[mi][3] = *reinterpret_cast<const uint32_t*>(pH + 8 * AST + 8);
                al[mi][0] = *reinterpret_cast<const uint32_t*>(pL);
                al[mi][1] = *reinterpret_cast<const uint32_t*>(pL + 8 * AST);
                al[mi][2] = *reinterpret_cast<const uint32_t*>(pL + 8);
                al[mi][3] = *reinterpret_cast<const uint32_t*>(pL + 8 * AST + 8);
            }
#pragma unroll
            for (int ni = 0; ni < 4; ni++) {
                const uint16_t* pH = &Bs_h[(wn * 32 + ni * 8 + g) * AST + ks * 16 + tq * 2];
                const uint16_t* pL = &Bs_l[(wn * 32 + ni * 8 + g) * AST + ks * 16 + tq * 2];
                bh[ni][0] = *reinterpret_cast<const uint32_t*>(pH);
                bh[ni][1] = *reinterpret_cast<const uint32_t*>(pH + 8);
                bl[ni][0] = *reinterpret_cast<const uint32_t*>(pL);
                bl[ni][1] = *reinterpret_cast<const uint32_t*>(pL + 8);
            }
#pragma unroll
            for (int mi = 0; mi < 2; mi++)
#pragma unroll
                for (int ni = 0; ni < 4; ni++) {
                    mma_bf16(acc[mi][ni], ah[mi], bh[ni]);   // hi*hi
                    mma_bf16(acc[mi][ni], ah[mi], bl[ni]);   // hi*lo
                    mma_bf16(acc[mi][ni], al[mi], bh[ni]);   // lo*hi
                }
        }
        __syncthreads();
    }

#pragma unroll
    for (int mi = 0; mi < 2; mi++)
#pragma unroll
        for (int ni = 0; ni < 4; ni++) {
            int row0 = m0 + wm * 32 + mi * 16 + g;
            int col  = wn * 32 + ni * 8 + tq * 2;
            if (row0 < NN)
                *reinterpret_cast<float2*>(&g_Y1[(size_t)row0 * HID_F + col]) =
                    make_float2(acc[mi][ni][0], acc[mi][ni][1]);
            if (row0 + 8 < NN)
                *reinterpret_cast<float2*>(&g_Y1[(size_t)(row0 + 8) * HID_F + col]) =
                    make_float2(acc[mi][ni][2], acc[mi][ni][3]);
        }
}

// ---------------- GEMM2: Y2 = X2 @ W2 (X2 already split-bf16) ---------------
// BM=64, BN=64, BK=32, 256 threads (8 warps, 2x4), warp tile 32x16.
__global__ void __launch_bounds__(256) gemm2_k() {
    __shared__ uint16_t As_h[64 * AST], As_l[64 * AST];
    __shared__ uint16_t Bs_h[64 * AST], Bs_l[64 * AST];

    const int tid  = threadIdx.x;
    const int lane = tid & 31;
    const int wid  = tid >> 5;
    const int wm   = wid >> 2;
    const int wn   = wid & 3;
    const int g    = lane >> 2;
    const int tq   = lane & 3;
    const int m0   = blockIdx.x * 64;

    float acc[2][2][4];
#pragma unroll
    for (int mi = 0; mi < 2; mi++)
#pragma unroll
        for (int ni = 0; ni < 2; ni++)
#pragma unroll
            for (int r = 0; r < 4; r++) acc[mi][ni][r] = 0.f;

    for (int kt = 0; kt < HID_F; kt += 32) {
        // A tile: 64 rows x 32 bf16 (hi/lo), 256 uint4 per array, 1 per thread.
        {
            int r = tid >> 2, c = tid & 3;
            int grow = m0 + r;
            uint4 vh = make_uint4(0u, 0u, 0u, 0u), vl = vh;
            if (grow < NN) {
                vh = *reinterpret_cast<const uint4*>(&g_X2h[(size_t)grow * HID_F + kt + c * 8]);
                vl = *reinterpret_cast<const uint4*>(&g_X2l[(size_t)grow * HID_F + kt + c * 8]);
            }
            *reinterpret_cast<uint4*>(&As_h[r * AST + c * 8]) = vh;
            *reinterpret_cast<uint4*>(&As_l[r * AST + c * 8]) = vl;
        }
        // B tile: 64 rows x 32 bf16 from W2^T, 256 uint4 per array, 1 per thread.
        {
            int n = tid >> 2, c = tid & 3;
            *reinterpret_cast<uint4*>(&Bs_h[n * AST + c * 8]) =
                *reinterpret_cast<const uint4*>(&g_W2Th[n * HID_F + kt + c * 8]);
            *reinterpret_cast<uint4*>(&Bs_l[n * AST + c * 8]) =
                *reinterpret_cast<const uint4*>(&g_W2Tl[n * HID_F + kt + c * 8]);
        }
        __syncthreads();

#pragma unroll
        for (int ks = 0; ks < 2; ks++) {
            uint32_t ah[2][4], al[2][4], bh[2][2], bl[2][2];
#pragma unroll
            for (int mi = 0; mi < 2; mi++) {
                const uint16_t* pH = &As_h[(wm * 32 + mi * 16 + g) * AST + ks * 16 + tq * 2];
                const uint16_t* pL = &As_l[(wm * 32 + mi * 16 + g) * AST + ks * 16 + tq * 2];
                ah[mi][0] = *reinterpret_cast<const uint32_t*>(pH);
                ah[mi][1] = *reinterpret_cast<const uint32_t*>(pH + 8 * AST);
                ah[mi][2] = *reinterpret_cast<const uint32_t*>(pH + 8);
                ah[mi][3] = *reinterpret_cast<const uint32_t*>(pH + 8 * AST + 8);
                al[mi][0] = *reinterpret_cast<const uint32_t*>(pL);
                al[mi][1] = *reinterpret_cast<const uint32_t*>(pL + 8 * AST);
                al[mi][2] = *reinterpret_cast<const uint32_t*>(pL + 8);
                al[mi][3] = *reinterpret_cast<const uint32_t*>(pL + 8 * AST + 8);
            }
#pragma unroll
            for (int ni = 0; ni < 2; ni++) {
                const uint16_t* pH = &Bs_h[(wn * 16 + ni * 8 + g) * AST + ks * 16 + tq * 2];
                const uint16_t* pL = &Bs_l[(wn * 16 + ni * 8 + g) * AST + ks * 16 + tq * 2];
                bh[ni][0] = *reinterpret_cast<const uint32_t*>(pH);
                bh[ni][1] = *reinterpret_cast<const uint32_t*>(pH + 8);
                bl[ni][0] = *reinterpret_cast<const uint32_t*>(pL);
                bl[ni][1] = *reinterpret_cast<const uint32_t*>(pL + 8);
            }
#pragma unroll
            for (int mi = 0; mi < 2; mi++)
#pragma unroll
                for (int ni = 0; ni < 2; ni++) {
                    mma_bf16(acc[mi][ni], ah[mi], bh[ni]);
                    mma_bf16(acc[mi][ni], ah[mi], bl[ni]);
                    mma_bf16(acc[mi][ni], al[mi], bh[ni]);
                }
        }
        __syncthreads();
    }

#pragma unroll
    for (int mi = 0; mi < 2; mi++)
#pragma unroll
        for (int ni = 0; ni < 2; ni++) {
            int row0 = m0 + wm * 32 + mi * 16 + g;
            int col  = wn * 16 + ni * 8 + tq * 2;
            if (row0 < NN)
                *reinterpret_cast<float2*>(&g_Y2[(size_t)row0 * OUT_F + col]) =
                    make_float2(acc[mi][ni][0], acc[mi][ni][1]);
            if (row0 + 8 < NN)
                *reinterpret_cast<float2*>(&g_Y2[(size_t)(row0 + 8) * OUT_F + col]) =
                    make_float2(acc[mi][ni][2], acc[mi][ni][3]);
        }
}

// ---------------- CSR gather, layer 1 (emits split-bf16 X2) ------------------
__global__ void __launch_bounds__(256) gather1(const float* __restrict__ b1) {
    int node = blockIdx.x * 8 + (threadIdx.x >> 5);
    if (node >= NN) return;
    int lane  = threadIdx.x & 31;
    int start = g_offs[node];
    int cnt   = g_deg_in[node];

    float4 acc = make_float4(0.f, 0.f, 0.f, 0.f);
    for (int j0 = 0; j0 < cnt; j0 += 32) {
        int m  = min(32, cnt - j0);
        int id = (lane < m) ? __ldg(&g_csr_src[start + j0 + lane]) : 0;
        int j  = 0;
        for (; j + 4 <= m; j += 4) {
            int s0 = __shfl_sync(0xffffffffu, id, j);
            int s1 = __shfl_sync(0xffffffffu, id, j + 1);
            int s2 = __shfl_sync(0xffffffffu, id, j + 2);
            int s3 = __shfl_sync(0xffffffffu, id, j + 3);
            float4 v0 = *reinterpret_cast<const float4*>(&g_Y1[(size_t)s0 * HID_F + lane * 4]);
            float4 v1 = *reinterpret_cast<const float4*>(&g_Y1[(size_t)s1 * HID_F + lane * 4]);
            float4 v2 = *reinterpret_cast<const float4*>(&g_Y1[(size_t)s2 * HID_F + lane * 4]);
            float4 v3 = *reinterpret_cast<const float4*>(&g_Y1[(size_t)s3 * HID_F + lane * 4]);
            acc.x += v0.x + v1.x + v2.x + v3.x;
            acc.y += v0.y + v1.y + v2.y + v3.y;
            acc.z += v0.z + v1.z + v2.z + v3.z;
            acc.w += v0.w + v1.w + v2.w + v3.w;
        }
        for (; j < m; j++) {
            int s = __shfl_sync(0xffffffffu, id, j);
            float4 v = *reinterpret_cast<const float4*>(&g_Y1[(size_t)s * HID_F + lane * 4]);
            acc.x += v.x; acc.y += v.y; acc.z += v.z; acc.w += v.w;
        }
    }

    float di = g_din_inv[node], dd = g_dout_inv[node];
    float4 b = *reinterpret_cast<const float4*>(&b1[lane * 4]);
    float f0 = fmaxf(acc.x * di + b.x, 0.f) * dd;
    float f1 = fmaxf(acc.y * di + b.y, 0.f) * dd;
    float f2 = fmaxf(acc.z * di + b.z, 0.f) * dd;
    float f3 = fmaxf(acc.w * di + b.w, 0.f) * dd;
    uint32_t h01, l01, h23, l23;
    split2(f0, f1, h01, l01);
    split2(f2, f3, h23, l23);
    size_t o = (size_t)node * HID_F + lane * 4;
    *reinterpret_cast<uint2*>(&g_X2h[o]) = make_uint2(h01, h23);
    *reinterpret_cast<uint2*>(&g_X2l[o]) = make_uint2(l01, l23);
}

// ---------------- CSR gather, layer 2 ----------------------------------------
__global__ void __launch_bounds__(256) gather2(float* __restrict__ out,
                                               const float* __restrict__ b2) {
    int node = blockIdx.x * 8 + (threadIdx.x >> 5);
    if (node >= NN) return;
    int lane  = threadIdx.x & 31;
    int start = g_offs[node];
    int cnt   = g_deg_in[node];

    float2 acc = make_float2(0.f, 0.f);
    for (int j0 = 0; j0 < cnt; j0 += 32) {
        int m  = min(32, cnt - j0);
        int id = (lane < m) ? __ldg(&g_csr_src[start + j0 + lane]) : 0;
        int j  = 0;
        for (; j + 4 <= m; j += 4) {
            int s0 = __shfl_sync(0xffffffffu, id, j);
            int s1 = __shfl_sync(0xffffffffu, id, j + 1);
            int s2 = __shfl_sync(0xffffffffu, id, j + 2);
            int s3 = __shfl_sync(0xffffffffu, id, j + 3);
            float2 v0 = *reinterpret_cast<const float2*>(&g_Y2[(size_t)s0 * OUT_F + lane * 2]);
            float2 v1 = *reinterpret_cast<const float2*>(&g_Y2[(size_t)s1 * OUT_F + lane * 2]);
            float2 v2 = *reinterpret_cast<const float2*>(&g_Y2[(size_t)s2 * OUT_F + lane * 2]);
            float2 v3 = *reinterpret_cast<const float2*>(&g_Y2[(size_t)s3 * OUT_F + lane * 2]);
            acc.x += v0.x + v1.x + v2.x + v3.x;
            acc.y += v0.y + v1.y + v2.y + v3.y;
        }
        for (; j < m; j++) {
            int s = __shfl_sync(0xffffffffu, id, j);
            float2 v = *reinterpret_cast<const float2*>(&g_Y2[(size_t)s * OUT_F + lane * 2]);
            acc.x += v.x; acc.y += v.y;
        }
    }

    float di = g_din_inv[node];
    float2 b = *reinterpret_cast<const float2*>(&b2[lane * 2]);
    acc.x = acc.x * di + b.x;
    acc.y = acc.y * di + b.y;
    *reinterpret_cast<float2*>(&out[(size_t)node * OUT_F + lane * 2]) = acc;
}

// ---------------- launch ----------------------------------------------------
extern "C" void kernel_launch(void* const* d_in, const int* in_sizes, int n_in,
                              void* d_out, int out_size) {
    (void)in_sizes; (void)n_in; (void)out_size;
    const float* features = (const float*)d_in[0];
    const int*   src      = (const int*)  d_in[1];
    const int*   dst      = (const int*)  d_in[2];
    const float* W1       = (const float*)d_in[3];
    const float* b1       = (const float*)d_in[4];
    const float* W2       = (const float*)d_in[5];
    const float* b2       = (const float*)d_in[6];
    float*       out      = (float*)      d_out;

    const int TPB = 256;
    const int SCAN_BLOCKS = (NN + 1023) / 1024;

    // degrees + CSR build + weight prep
    zero_degs<<<(NN + TPB - 1) / TPB, TPB>>>();
    hist_kernel<<<(EE + TPB - 1) / TPB, TPB>>>(src, dst);
    deg_finalize<<<(NN + TPB - 1) / TPB, TPB>>>();
    scan_block_k<<<SCAN_BLOCKS, 1024>>>();
    scan_top_k<<<1, 128>>>(SCAN_BLOCKS);
    scan_add_k<<<SCAN_BLOCKS, 1024>>>();
    csr_fill<<<(EE + TPB - 1) / TPB, TPB>>>(src, dst);
    split_w1<<<(IN_F * HID_F + TPB - 1) / TPB, TPB>>>(W1);
    split_w2<<<(HID_F * OUT_F + TPB - 1) / TPB, TPB>>>(W2);

    // layer 1
    gemm1_k<<<(NN + 63) / 64, 256>>>(features);
    gather1<<<(NN + 7) / 8, TPB>>>(b1);

    // layer 2
    gemm2_k<<<(NN + 63) / 64, 256>>>();
    gather2<<<(NN + 7) / 8, TPB>>>(out, b2);
}

// round 11
// speedup vs baseline: 2.0897x; 1.0526x over previous
#include <cuda_runtime.h>
#include <cuda_bf16.h>
#include <cuda_fp16.h>
#include <cstdint>

#define NN     100000
#define EE     1600000
#define IN_F   256
#define HID_F  128
#define OUT_F  64

// ---------------- scratch (device globals; no runtime allocation) -----------
__device__ int   g_deg_out[NN];
__device__ int   g_deg_in [NN];
__device__ float g_dout_inv[NN];
__device__ float g_din_inv [NN];
__device__ int   g_offs  [NN];
__device__ int   g_cursor[NN];
__device__ int   g_bsums [128];
__device__ int   g_csr_src[EE];
__device__ __align__(16) __half g_Y1h[(size_t)NN * HID_F];       // layer1 GEMM out (fp16 messages)
__device__ __align__(16) uint16_t g_X2h[(size_t)NN * HID_F];     // X2 hi (bf16)
__device__ __align__(16) uint16_t g_X2l[(size_t)NN * HID_F];     // X2 lo (bf16)
__device__ float g_Y2[(size_t)NN * OUT_F];                       // layer2 GEMM out
__device__ __align__(16) uint16_t g_W1Th[HID_F * IN_F];          // W1^T hi  [n][k]
__device__ __align__(16) uint16_t g_W1Tl[HID_F * IN_F];          // W1^T lo
__device__ __align__(16) uint16_t g_W2Th[OUT_F * HID_F];         // W2^T hi  [n][k]
__device__ __align__(16) uint16_t g_W2Tl[OUT_F * HID_F];         // W2^T lo

// ---------------- helpers ---------------------------------------------------
__device__ __forceinline__ int warp_incl_scan(int x) {
#pragma unroll
    for (int d = 1; d < 32; d <<= 1) {
        int y = __shfl_up_sync(0xffffffffu, x, d);
        if ((threadIdx.x & 31) >= d) x += y;
    }
    return x;
}

// split fp32 pair -> packed bf16 hi / lo (x in low 16 bits)
__device__ __forceinline__ void split2(float x, float y, uint32_t& h, uint32_t& l) {
    __nv_bfloat16 hx = __float2bfloat16(x);
    __nv_bfloat16 hy = __float2bfloat16(y);
    __nv_bfloat16 lx = __float2bfloat16(x - __bfloat162float(hx));
    __nv_bfloat16 ly = __float2bfloat16(y - __bfloat162float(hy));
    h = (uint32_t)__bfloat16_as_ushort(hx) | ((uint32_t)__bfloat16_as_ushort(hy) << 16);
    l = (uint32_t)__bfloat16_as_ushort(lx) | ((uint32_t)__bfloat16_as_ushort(ly) << 16);
}

__device__ __forceinline__ void mma_bf16(float* c, const uint32_t* a, const uint32_t* b) {
    asm volatile(
        "mma.sync.aligned.m16n8k16.row.col.f32.bf16.bf16.f32 "
        "{%0,%1,%2,%3}, {%4,%5,%6,%7}, {%8,%9}, {%0,%1,%2,%3};\n"
        : "+f"(c[0]), "+f"(c[1]), "+f"(c[2]), "+f"(c[3])
        : "r"(a[0]), "r"(a[1]), "r"(a[2]), "r"(a[3]), "r"(b[0]), "r"(b[1]));
}

// accumulate 4 fp16 feats (8 bytes) into float4
__device__ __forceinline__ void acc_h4(float4& acc, const __half* p) {
    uint2 u = *reinterpret_cast<const uint2*>(p);
    __half2 ha = *reinterpret_cast<const __half2*>(&u.x);
    __half2 hb = *reinterpret_cast<const __half2*>(&u.y);
    float2 fa = __half22float2(ha);
    float2 fb = __half22float2(hb);
    acc.x += fa.x; acc.y += fa.y; acc.z += fb.x; acc.w += fb.y;
}

// ---------------- degrees / scan / CSR --------------------------------------
__global__ void zero_degs() {
    int i = blockIdx.x * blockDim.x + threadIdx.x;
    if (i < NN) { g_deg_out[i] = 0; g_deg_in[i] = 0; }
}

__global__ void hist_kernel(const int* __restrict__ src, const int* __restrict__ dst) {
    int e = blockIdx.x * blockDim.x + threadIdx.x;
    if (e < EE) {
        atomicAdd(&g_deg_out[src[e]], 1);
        atomicAdd(&g_deg_in [dst[e]], 1);
    }
}

__global__ void scan_block_k() {
    __shared__ int wsum[32];
    int i = blockIdx.x * 1024 + threadIdx.x;
    int v = (i < NN) ? g_deg_in[i] : 0;
    int x = warp_incl_scan(v);
    if ((threadIdx.x & 31) == 31) wsum[threadIdx.x >> 5] = x;
    __syncthreads();
    if (threadIdx.x < 32) {
        int w  = wsum[threadIdx.x];
        int wx = warp_incl_scan(w);
        wsum[threadIdx.x] = wx - w;
        if (threadIdx.x == 31) g_bsums[blockIdx.x] = wx;
    }
    __syncthreads();
    int excl = x - v + wsum[threadIdx.x >> 5];
    if (i < NN) g_offs[i] = excl;
}

__global__ void scan_top_k(int nb) {
    __shared__ int wsum[4];
    int t = threadIdx.x;
    int v = (t < nb) ? g_bsums[t] : 0;
    int x = warp_incl_scan(v);
    if ((t & 31) == 31) wsum[t >> 5] = x;
    __syncthreads();
    if (t == 0) {
        int run = 0;
#pragma unroll
        for (int w = 0; w < 4; w++) { int tmp = wsum[w]; wsum[w] = run; run += tmp; }
    }
    __syncthreads();
    int excl = x - v + wsum[t >> 5];
    if (t < nb) g_bsums[t] = excl;
}

// fused: finalize offsets/cursors AND compute degree normalizers
__global__ void scan_add_k() {
    int i = blockIdx.x * 1024 + threadIdx.x;
    if (i < NN) {
        int o = g_offs[i] + g_bsums[blockIdx.x];
        g_offs[i]   = o;
        g_cursor[i] = o;
        g_dout_inv[i] = rsqrtf(fmaxf((float)g_deg_out[i], 1.0f));
        g_din_inv[i]  = rsqrtf(fmaxf((float)g_deg_in[i],  1.0f));
    }
}

__global__ void csr_fill(const int* __restrict__ src, const int* __restrict__ dst) {
    int e = blockIdx.x * blockDim.x + threadIdx.x;
    if (e < EE) {
        int pos = atomicAdd(&g_cursor[dst[e]], 1);
        g_csr_src[pos] = src[e];
    }
}

// ---------------- weight split/transpose ------------------------------------
__global__ void split_w1(const float* __restrict__ W1) {       // [256,128] -> [128][256]
    int idx = blockIdx.x * blockDim.x + threadIdx.x;
    if (idx < IN_F * HID_F) {
        int k = idx / HID_F, n = idx % HID_F;
        float v = W1[idx];
        __nv_bfloat16 h = __float2bfloat16(v);
        __nv_bfloat16 l = __float2bfloat16(v - __bfloat162float(h));
        g_W1Th[n * IN_F + k] = __bfloat16_as_ushort(h);
        g_W1Tl[n * IN_F + k] = __bfloat16_as_ushort(l);
    }
}

__global__ void split_w2(const float* __restrict__ W2) {       // [128,64] -> [64][128]
    int idx = blockIdx.x * blockDim.x + threadIdx.x;
    if (idx < HID_F * OUT_F) {
        int k = idx / OUT_F, n = idx % OUT_F;
        float v = W2[idx];
        __nv_bfloat16 h = __float2bfloat16(v);
        __nv_bfloat16 l = __float2bfloat16(v - __bfloat162float(h));
        g_W2Th[n * HID_F + k] = __bfloat16_as_ushort(h);
        g_W2Tl[n * HID_F + k] = __bfloat16_as_ushort(l);
    }
}

// ---------------- GEMM1: Y1 = (X * dout) @ W1, split-bf16 tensor cores ------
// BM=64, BN=128, BK=32, 256 threads (8 warps, 2x4), warp tile 32x32.
#define AST 40   // padded smem row stride (bf16 elems) -> conflict-free frag loads
__global__ void __launch_bounds__(256) gemm1_k(const float* __restrict__ A) {
    __shared__ uint16_t As_h[64 * AST],  As_l[64 * AST];
    __shared__ uint16_t Bs_h[128 * AST], Bs_l[128 * AST];

    const int tid  = threadIdx.x;
    const int lane = tid & 31;
    const int wid  = tid >> 5;
    const int wm   = wid >> 2;                 // 0..1
    const int wn   = wid & 3;                  // 0..3
    const int g    = lane >> 2;
    const int tq   = lane & 3;
    const int m0   = blockIdx.x * 64;

    float acc[2][4][4];
#pragma unroll
    for (int mi = 0; mi < 2; mi++)
#pragma unroll
        for (int ni = 0; ni < 4; ni++)
#pragma unroll
            for (int r = 0; r < 4; r++) acc[mi][ni][r] = 0.f;

    for (int kt = 0; kt < IN_F; kt += 32) {
        // A tile: 64x32 fp32 -> scale -> split bf16. 512 float4, 2 per thread.
#pragma unroll
        for (int i = 0; i < 2; i++) {
            int idx = tid + i * 256;
            int r = idx >> 3, c = idx & 7;
            int grow = m0 + r;
            float4 v = make_float4(0.f, 0.f, 0.f, 0.f);
            if (grow < NN) {
                v = *reinterpret_cast<const float4*>(&A[(size_t)grow * IN_F + kt + c * 4]);
                float s = g_dout_inv[grow];
                v.x *= s; v.y *= s; v.z *= s; v.w *= s;
            }
            uint32_t h01, l01, h23, l23;
            split2(v.x, v.y, h01, l01);
            split2(v.z, v.w, h23, l23);
            *reinterpret_cast<uint32_t*>(&As_h[r * AST + c * 4])     = h01;
            *reinterpret_cast<uint32_t*>(&As_h[r * AST + c * 4 + 2]) = h23;
            *reinterpret_cast<uint32_t*>(&As_l[r * AST + c * 4])     = l01;
            *reinterpret_cast<uint32_t*>(&As_l[r * AST + c * 4 + 2]) = l23;
        }
        // B tile: 128 rows x 32 bf16 from pre-split W1^T. 512 uint4, 2 per thread.
#pragma unroll
        for (int i = 0; i < 2; i++) {
            int idx = tid + i * 256;
            int n = idx >> 2, c = idx & 3;
            *reinterpret_cast<uint4*>(&Bs_h[n * AST + c * 8]) =
                *reinterpret_cast<const uint4*>(&g_W1Th[n * IN_F + kt + c * 8]);
            *reinterpret_cast<uint4*>(&Bs_l[n * AST + c * 8]) =
                *reinterpret_cast<const uint4*>(&g_W1Tl[n * IN_F + kt + c * 8]);
        }
        __syncthreads();

#pragma unroll
        for (int ks = 0; ks < 2; ks++) {
            uint32_t ah[2][4], al[2][4], bh[4][2], bl[4][2];
#pragma unroll
            for (int mi = 0; mi < 2; mi++) {
                const uint16_t* pH = &As_h[(wm * 32 + mi * 16 + g) * AST + ks * 16 + tq * 2];
                const uint16_t* pL = &As_l[(wm * 32 + mi * 16 + g) * AST + ks * 16 + tq * 2];
                ah[mi][0] = *reinterpret_cast<const uint32_t*>(pH);
                ah[mi][1] = *reinterpret_cast<const uint32_t*>(pH + 8 * AST);
                ah[mi][2] = *reinterpret_cast<const uint32_t*>(pH + 8);
                ah[mi][3] = *reinterpret_cast<const uint32_t*>(pH + 8 * AST + 8);
                al[mi][0] = *reinterpret_cast<const uint32_t*>(pL);
                al[mi][1] = *reinterpret_cast<const uint32_t*>(pL + 8 * AST);
                al[mi][2] = *reinterpret_cast<const uint32_t*>(pL + 8);
                al[mi][3] = *reinterpret_cast<const uint32_t*>(pL + 8 * AST + 8);
            }
#pragma unroll
            for (int ni = 0; ni < 4; ni++) {
                const uint16_t* pH = &Bs_h[(wn * 32 + ni * 8 + g) * AST + ks * 16 + tq * 2];
                const uint16_t* pL = &Bs_l[(wn * 32 + ni * 8 + g) * AST + ks * 16 + tq * 2];
                bh[ni][0] = *reinterpret_cast<const uint32_t*>(pH);
                bh[ni][1] = *reinterpret_cast<const uint32_t*>(pH + 8);
                bl[ni][0] = *reinterpret_cast<const uint32_t*>(pL);
                bl[ni][1] = *reinterpret_cast<const uint32_t*>(pL + 8);
            }
#pragma unroll
            for (int mi = 0; mi < 2; mi++)
#pragma unroll
                for (int ni = 0; ni < 4; ni++) {
                    mma_bf16(acc[mi][ni], ah[mi], bh[ni]);   // hi*hi
                    mma_bf16(acc[mi][ni], ah[mi], bl[ni]);   // hi*lo
                    mma_bf16(acc[mi][ni], al[mi], bh[ni]);   // lo*hi
                }
        }
        __syncthreads();
    }

    // epilogue: write fp16 messages (half traffic for gather1)
#pragma unroll
    for (int mi = 0; mi < 2; mi++)
#pragma unroll
        for (int ni = 0; ni < 4; ni++) {
            int row0 = m0 + wm * 32 + mi * 16 + g;
            int col  = wn * 32 + ni * 8 + tq * 2;
            if (row0 < NN)
                *reinterpret_cast<__half2*>(&g_Y1h[(size_t)row0 * HID_F + col]) =
                    __floats2half2_rn(acc[mi][ni][0], acc[mi][ni][1]);
            if (row0 + 8 < NN)
                *reinterpret_cast<__half2*>(&g_Y1h[(size_t)(row0 + 8) * HID_F + col]) =
                    __floats2half2_rn(acc[mi][ni][2], acc[mi][ni][3]);
        }
}

// ---------------- GEMM2: Y2 = X2 @ W2 (X2 already split-bf16) ---------------
// BM=64, BN=64, BK=32, 256 threads (8 warps, 2x4), warp tile 32x16.
__global__ void __launch_bounds__(256) gemm2_k() {
    __shared__ uint16_t As_h[64 * AST], As_l[64 * AST];
    __shared__ uint16_t Bs_h[64 * AST], Bs_l[64 * AST];

    const int tid  = threadIdx.x;
    const int lane = tid & 31;
    const int wid  = tid >> 5;
    const int wm   = wid >> 2;
    const int wn   = wid & 3;
    const int g    = lane >> 2;
    const int tq   = lane & 3;
    const int m0   = blockIdx.x * 64;

    float acc[2][2][4];
#pragma unroll
    for (int mi = 0; mi < 2; mi++)
#pragma unroll
        for (int ni = 0; ni < 2; ni++)
#pragma unroll
            for (int r = 0; r < 4; r++) acc[mi][ni][r] = 0.f;

    for (int kt = 0; kt < HID_F; kt += 32) {
        // A tile: 64 rows x 32 bf16 (hi/lo), 256 uint4 per array, 1 per thread.
        {
            int r = tid >> 2, c = tid & 3;
            int grow = m0 + r;
            uint4 vh = make_uint4(0u, 0u, 0u, 0u), vl = vh;
            if (grow < NN) {
                vh = *reinterpret_cast<const uint4*>(&g_X2h[(size_t)grow * HID_F + kt + c * 8]);
                vl = *reinterpret_cast<const uint4*>(&g_X2l[(size_t)grow * HID_F + kt + c * 8]);
            }
            *reinterpret_cast<uint4*>(&As_h[r * AST + c * 8]) = vh;
            *reinterpret_cast<uint4*>(&As_l[r * AST + c * 8]) = vl;
        }
        // B tile: 64 rows x 32 bf16 from W2^T, 256 uint4 per array, 1 per thread.
        {
            int n = tid >> 2, c = tid & 3;
            *reinterpret_cast<uint4*>(&Bs_h[n * AST + c * 8]) =
                *reinterpret_cast<const uint4*>(&g_W2Th[n * HID_F + kt + c * 8]);
            *reinterpret_cast<uint4*>(&Bs_l[n * AST + c * 8]) =
                *reinterpret_cast<const uint4*>(&g_W2Tl[n * HID_F + kt + c * 8]);
        }
        __syncthreads();

#pragma unroll
        for (int ks = 0; ks < 2; ks++) {
            uint32_t ah[2][4], al[2][4], bh[2][2], bl[2][2];
#pragma unroll
            for (int mi = 0; mi < 2; mi++) {
                const uint16_t* pH = &As_h[(wm * 32 + mi * 16 + g) * AST + ks * 16 + tq * 2];
                const uint16_t* pL = &As_l[(wm * 32 + mi * 16 + g) * AST + ks * 16 + tq * 2];
                ah[mi][0] = *reinterpret_cast<const uint32_t*>(pH);
                ah[mi][1] = *reinterpret_cast<const uint32_t*>(pH + 8 * AST);
                ah[mi][2] = *reinterpret_cast<const uint32_t*>(pH + 8);
                ah[mi][3] = *reinterpret_cast<const uint32_t*>(pH + 8 * AST + 8);
                al[mi][0] = *reinterpret_cast<const uint32_t*>(pL);
                al[mi][1] = *reinterpret_cast<const uint32_t*>(pL + 8 * AST);
                al[mi][2] = *reinterpret_cast<const uint32_t*>(pL + 8);
                al[mi][3] = *reinterpret_cast<const uint32_t*>(pL + 8 * AST + 8);
            }
#pragma unroll
            for (int ni = 0; ni < 2; ni++) {
                const uint16_t* pH = &Bs_h[(wn * 16 + ni * 8 + g) * AST + ks * 16 + tq * 2];
                const uint16_t* pL = &Bs_l[(wn * 16 + ni * 8 + g) * AST + ks * 16 + tq * 2];
                bh[ni][0] = *reinterpret_cast<const uint32_t*>(pH);
                bh[ni][1] = *reinterpret_cast<const uint32_t*>(pH + 8);
                bl[ni][0] = *reinterpret_cast<const uint32_t*>(pL);
                bl[ni][1] = *reinterpret_cast<const uint32_t*>(pL + 8);
            }
#pragma unroll
            for (int mi = 0; mi < 2; mi++)
#pragma unroll
                for (int ni = 0; ni < 2; ni++) {
                    mma_bf16(acc[mi][ni], ah[mi], bh[ni]);
                    mma_bf16(acc[mi][ni], ah[mi], bl[ni]);
                    mma_bf16(acc[mi][ni], al[mi], bh[ni]);
                }
        }
        __syncthreads();
    }

#pragma unroll
    for (int mi = 0; mi < 2; mi++)
#pragma unroll
        for (int ni = 0; ni < 2; ni++) {
            int row0 = m0 + wm * 32 + mi * 16 + g;
            int col  = wn * 16 + ni * 8 + tq * 2;
            if (row0 < NN)
                *reinterpret_cast<float2*>(&g_Y2[(size_t)row0 * OUT_F + col]) =
                    make_float2(acc[mi][ni][0], acc[mi][ni][1]);
            if (row0 + 8 < NN)
                *reinterpret_cast<float2*>(&g_Y2[(size_t)(row0 + 8) * OUT_F + col]) =
                    make_float2(acc[mi][ni][2], acc[mi][ni][3]);
        }
}

// ---------------- CSR gather, layer 1 (fp16 in, split-bf16 X2 out) -----------
__global__ void __launch_bounds__(256) gather1(const float* __restrict__ b1) {
    int node = blockIdx.x * 8 + (threadIdx.x >> 5);
    if (node >= NN) return;
    int lane  = threadIdx.x & 31;
    int start = g_offs[node];
    int cnt   = g_deg_in[node];

    float4 acc = make_float4(0.f, 0.f, 0.f, 0.f);
    for (int j0 = 0; j0 < cnt; j0 += 32) {
        int m  = min(32, cnt - j0);
        int id = (lane < m) ? __ldg(&g_csr_src[start + j0 + lane]) : 0;
        int j  = 0;
        for (; j + 4 <= m; j += 4) {
            int s0 = __shfl_sync(0xffffffffu, id, j);
            int s1 = __shfl_sync(0xffffffffu, id, j + 1);
            int s2 = __shfl_sync(0xffffffffu, id, j + 2);
            int s3 = __shfl_sync(0xffffffffu, id, j + 3);
            acc_h4(acc, &g_Y1h[(size_t)s0 * HID_F + lane * 4]);
            acc_h4(acc, &g_Y1h[(size_t)s1 * HID_F + lane * 4]);
            acc_h4(acc, &g_Y1h[(size_t)s2 * HID_F + lane * 4]);
            acc_h4(acc, &g_Y1h[(size_t)s3 * HID_F + lane * 4]);
        }
        for (; j < m; j++) {
            int s = __shfl_sync(0xffffffffu, id, j);
            acc_h4(acc, &g_Y1h[(size_t)s * HID_F + lane * 4]);
        }
    }

    float di = g_din_inv[node], dd = g_dout_inv[node];
    float4 b = *reinterpret_cast<const float4*>(&b1[lane * 4]);
    float f0 = fmaxf(acc.x * di + b.x, 0.f) * dd;
    float f1 = fmaxf(acc.y * di + b.y, 0.f) * dd;
    float f2 = fmaxf(acc.z * di + b.z, 0.f) * dd;
    float f3 = fmaxf(acc.w * di + b.w, 0.f) * dd;
    uint32_t h01, l01, h23, l23;
    split2(f0, f1, h01, l01);
    split2(f2, f3, h23, l23);
    size_t o = (size_t)node * HID_F + lane * 4;
    *reinterpret_cast<uint2*>(&g_X2h[o]) = make_uint2(h01, h23);
    *reinterpret_cast<uint2*>(&g_X2l[o]) = make_uint2(l01, l23);
}

// ---------------- CSR gather, layer 2 ----------------------------------------
__global__ void __launch_bounds__(256) gather2(float* __restrict__ out,
                                               const float* __restrict__ b2) {
    int node = blockIdx.x * 8 + (threadIdx.x >> 5);
    if (node >= NN) return;
    int lane  = threadIdx.x & 31;
    int start = g_offs[node];
    int cnt   = g_deg_in[node];

    float2 acc = make_float2(0.f, 0.f);
    for (int j0 = 0; j0 < cnt; j0 += 32) {
        int m  = min(32, cnt - j0);
        int id = (lane < m) ? __ldg(&g_csr_src[start + j0 + lane]) : 0;
        int j  = 0;
        for (; j + 4 <= m; j += 4) {
            int s0 = __shfl_sync(0xffffffffu, id, j);
            int s1 = __shfl_sync(0xffffffffu, id, j + 1);
            int s2 = __shfl_sync(0xffffffffu, id, j + 2);
            int s3 = __shfl_sync(0xffffffffu, id, j + 3);
            float2 v0 = *reinterpret_cast<const float2*>(&g_Y2[(size_t)s0 * OUT_F + lane * 2]);
            float2 v1 = *reinterpret_cast<const float2*>(&g_Y2[(size_t)s1 * OUT_F + lane * 2]);
            float2 v2 = *reinterpret_cast<const float2*>(&g_Y2[(size_t)s2 * OUT_F + lane * 2]);
            float2 v3 = *reinterpret_cast<const float2*>(&g_Y2[(size_t)s3 * OUT_F + lane * 2]);
            acc.x += v0.x + v1.x + v2.x + v3.x;
            acc.y += v0.y + v1.y + v2.y + v3.y;
        }
        for (; j < m; j++) {
            int s = __shfl_sync(0xffffffffu, id, j);
            float2 v = *reinterpret_cast<const float2*>(&g_Y2[(size_t)s * OUT_F + lane * 2]);
            acc.x += v.x; acc.y += v.y;
        }
    }

    float di = g_din_inv[node];
    float2 b = *reinterpret_cast<const float2*>(&b2[lane * 2]);
    acc.x = acc.x * di + b.x;
    acc.y = acc.y * di + b.y;
    *reinterpret_cast<float2*>(&out[(size_t)node * OUT_F + lane * 2]) = acc;
}

// ---------------- launch ----------------------------------------------------
extern "C" void kernel_launch(void* const* d_in, const int* in_sizes, int n_in,
                              void* d_out, int out_size) {
    (void)in_sizes; (void)n_in; (void)out_size;
    const float* features = (const float*)d_in[0];
    const int*   src      = (const int*)  d_in[1];
    const int*   dst      = (const int*)  d_in[2];
    const float* W1       = (const float*)d_in[3];
    const float* b1       = (const float*)d_in[4];
    const float* W2       = (const float*)d_in[5];
    const float* b2       = (const float*)d_in[6];
    float*       out      = (float*)      d_out;

    const int TPB = 256;
    const int SCAN_BLOCKS = (NN + 1023) / 1024;

    // degrees + CSR build + weight prep
    zero_degs<<<(NN + TPB - 1) / TPB, TPB>>>();
    hist_kernel<<<(EE + TPB - 1) / TPB, TPB>>>(src, dst);
    scan_block_k<<<SCAN_BLOCKS, 1024>>>();
    scan_top_k<<<1, 128>>>(SCAN_BLOCKS);
    scan_add_k<<<SCAN_BLOCKS, 1024>>>();          // also computes deg normalizers
    csr_fill<<<(EE + TPB - 1) / TPB, TPB>>>(src, dst);
    split_w1<<<(IN_F * HID_F + TPB - 1) / TPB, TPB>>>(W1);
    split_w2<<<(HID_F * OUT_F + TPB - 1) / TPB, TPB>>>(W2);

    // layer 1
    gemm1_k<<<(NN + 63) / 64, 256>>>(features);
    gather1<<<(NN + 7) / 8, TPB>>>(b1);

    // layer 2
    gemm2_k<<<(NN + 63) / 64, 256>>>();
    gather2<<<(NN + 7) / 8, TPB>>>(out, b2);
}